// round 2
// baseline (speedup 1.0000x reference)
#include <cuda_runtime.h>
#include <cuda_bf16.h>

// ---------------------------------------------------------------------------
// graph_encoder: B=16, N=1024 (E=767 ents + R=256 rels + 1 root), H=256,
// 4 heads, 2 layers.  Baseline fp32 implementation.
// ---------------------------------------------------------------------------

#define Bsz   16
#define Nn    1024
#define Hd    256
#define Ee    767
#define Rr    256
#define ROOTI 46
#define Mrows (Bsz * Nn)            // 16384
#define XSZ   (Mrows * Hd)          // 4,194,304
#define H1SZ  (Mrows * 4 * Hd)      // 16,777,216

// scratch (device globals: no allocation allowed)
__device__ float g_x [XSZ];
__device__ float g_q [XSZ];
__device__ float g_k [XSZ];
__device__ float g_v [XSZ];
__device__ float g_o [XSZ];
__device__ float g_t [XSZ];
__device__ float g_h2[XSZ];
__device__ float g_h1[H1SZ];

// ---------------------------------------------------------------------------
// Embedding gather: x[b,n,:] = ent/rel/root embedding
// grid: B*N blocks, 256 threads
// ---------------------------------------------------------------------------
__global__ void embed_kernel(const int* __restrict__ ents,
                             const int* __restrict__ rels,
                             const float* __restrict__ ent_table,
                             const float* __restrict__ rel_table,
                             float* __restrict__ x)
{
    int bn = blockIdx.x;
    int b  = bn >> 10;
    int n  = bn & 1023;
    const float* src;
    if (n < Ee)            src = ent_table + (size_t)ents[b * Ee + n] * Hd;
    else if (n < Ee + Rr)  src = rel_table + (size_t)rels[b * Rr + (n - Ee)] * Hd;
    else                   src = rel_table + (size_t)ROOTI * Hd;
    x[(size_t)bn * Hd + threadIdx.x] = src[threadIdx.x];
}

// ---------------------------------------------------------------------------
// Generic tiled fp32 GEMM: C[M,Nc] = A[M,K] @ W[K,Nc] (+ bias, + PReLU)
// 64x64 tile, TK=16, 256 threads, 4x4 per-thread microtile.
// mode: 0 = plain, 1 = bias + PReLU(alpha), 2 = bias only
// ---------------------------------------------------------------------------
__global__ void gemm_kernel(const float* __restrict__ A,
                            const float* __restrict__ W,
                            float* __restrict__ C,
                            int M, int K, int Nc,
                            const float* __restrict__ bias,
                            const float* __restrict__ alpha,
                            int mode)
{
    __shared__ float As[16][64];
    __shared__ float Bs[16][64];

    int t  = threadIdx.x;
    int tx = t & 15;
    int ty = t >> 4;
    int row0 = blockIdx.y << 6;
    int col0 = blockIdx.x << 6;

    float acc[4][4] = {};

    const float* Ap = A + (size_t)row0 * K;
    const float* Wp = W + col0;

    for (int k0 = 0; k0 < K; k0 += 16) {
#pragma unroll
        for (int i = 0; i < 4; i++) {
            int idx = t + i * 256;          // 0..1023
            int m  = idx >> 4;
            int kk = idx & 15;
            As[kk][m] = Ap[(size_t)m * K + k0 + kk];
        }
#pragma unroll
        for (int i = 0; i < 4; i++) {
            int idx = t + i * 256;
            int kk = idx >> 6;
            int n  = idx & 63;
            Bs[kk][n] = Wp[(size_t)(k0 + kk) * Nc + n];
        }
        __syncthreads();
#pragma unroll
        for (int kk = 0; kk < 16; kk++) {
            float a0 = As[kk][ty * 4 + 0];
            float a1 = As[kk][ty * 4 + 1];
            float a2 = As[kk][ty * 4 + 2];
            float a3 = As[kk][ty * 4 + 3];
            float4 bv = *(const float4*)&Bs[kk][tx * 4];
            acc[0][0] += a0 * bv.x; acc[0][1] += a0 * bv.y; acc[0][2] += a0 * bv.z; acc[0][3] += a0 * bv.w;
            acc[1][0] += a1 * bv.x; acc[1][1] += a1 * bv.y; acc[1][2] += a1 * bv.z; acc[1][3] += a1 * bv.w;
            acc[2][0] += a2 * bv.x; acc[2][1] += a2 * bv.y; acc[2][2] += a2 * bv.z; acc[2][3] += a2 * bv.w;
            acc[3][0] += a3 * bv.x; acc[3][1] += a3 * bv.y; acc[3][2] += a3 * bv.z; acc[3][3] += a3 * bv.w;
        }
        __syncthreads();
    }

#pragma unroll
    for (int u = 0; u < 4; u++) {
        int r = row0 + ty * 4 + u;
#pragma unroll
        for (int v = 0; v < 4; v++) {
            int c = col0 + tx * 4 + v;
            float val = acc[u][v];
            if (mode != 0) val += bias[c];
            if (mode == 1) val = (val >= 0.f) ? val : alpha[c] * val;
            C[(size_t)r * Nc + c] = val;
        }
    }
}

// ---------------------------------------------------------------------------
// Attention: block = (i-tile of 4 query rows, batch b). 256 threads.
// dynamic smem: q[4*256] | s[16*1024] | red[256] | invs[16]
// ---------------------------------------------------------------------------
#define ATTN_SMEM ((4 * 256 + 16 * 1024 + 256 + 16) * sizeof(float))

__global__ void attn_kernel(const float* __restrict__ Q,
                            const float* __restrict__ K,
                            const float* __restrict__ V,
                            const float* __restrict__ X,
                            const int* __restrict__ adj,
                            float* __restrict__ O)
{
    extern __shared__ float smem[];
    float* q    = smem;                 // [4][256]
    float* s    = smem + 1024;          // [16][1024]   (i*4+h , j)
    float* red  = s + 16 * 1024;        // [256]
    float* invs = red + 256;            // [16]

    int t  = threadIdx.x;
    int b  = blockIdx.y;
    int i0 = blockIdx.x << 2;

    // load 4 query rows (contiguous) into smem
#pragma unroll
    for (int i = t; i < 4 * Hd; i += 256)
        q[i] = Q[((size_t)(b * Nn + i0)) * Hd + i];
    __syncthreads();

    const float* Kb = K + (size_t)b * Nn * Hd;

    // -------- scores --------
#pragma unroll
    for (int jj = 0; jj < 4; jj++) {
        int j = (jj << 8) + t;
        const float4* kr = (const float4*)(Kb + (size_t)j * Hd);
        int adjv[4];
#pragma unroll
        for (int i = 0; i < 4; i++)
            adjv[i] = adj[((size_t)(b * Nn + i0 + i)) * Nn + j];

#pragma unroll
        for (int h = 0; h < 4; h++) {
            float4 kregs[16];
#pragma unroll
            for (int d = 0; d < 16; d++) kregs[d] = kr[h * 16 + d];
#pragma unroll
            for (int i = 0; i < 4; i++) {
                const float4* qi = (const float4*)(q + i * Hd + h * 64);
                float a = 0.f;
#pragma unroll
                for (int d = 0; d < 16; d++) {
                    float4 qv = qi[d];
                    a += kregs[d].x * qv.x + kregs[d].y * qv.y
                       + kregs[d].z * qv.z + kregs[d].w * qv.w;
                }
                s[((i * 4 + h) << 10) + j] = adjv[i] ? a * 0.0625f : -1e30f;
            }
        }
    }
    __syncthreads();

    // -------- softmax per (i,h): 16 groups x 16 threads --------
    int g = t >> 4;          // 0..15 = i*4+h
    int l = t & 15;
    float* sg = s + (g << 10);

    float mx = -1e30f;
    for (int j = l; j < Nn; j += 16) mx = fmaxf(mx, sg[j]);
    red[t] = mx;
    __syncthreads();
#pragma unroll
    for (int off = 8; off > 0; off >>= 1) {
        if (l < off) red[t] = fmaxf(red[t], red[t + off]);
        __syncthreads();
    }
    mx = red[t & ~15];
    __syncthreads();

    float sum = 0.f;
    for (int j = l; j < Nn; j += 16) {
        float e = __expf(sg[j] - mx);
        sg[j] = e;
        sum += e;
    }
    red[t] = sum;
    __syncthreads();
#pragma unroll
    for (int off = 8; off > 0; off >>= 1) {
        if (l < off) red[t] += red[t + off];
        __syncthreads();
    }
    if (l == 0) invs[g] = 1.f / red[t];
    __syncthreads();

    // -------- output: column t for 4 query rows --------
    int h = t >> 6;
    const float* Vb = V + (size_t)b * Nn * Hd + t;
    float acc0 = 0.f, acc1 = 0.f, acc2 = 0.f, acc3 = 0.f;
    const float* s0 = s + ((0 * 4 + h) << 10);
    const float* s1 = s + ((1 * 4 + h) << 10);
    const float* s2 = s + ((2 * 4 + h) << 10);
    const float* s3 = s + ((3 * 4 + h) << 10);
#pragma unroll 4
    for (int j = 0; j < Nn; j++) {
        float vv = Vb[(size_t)j * Hd];
        acc0 += s0[j] * vv;
        acc1 += s1[j] * vv;
        acc2 += s2[j] * vv;
        acc3 += s3[j] * vv;
    }
    size_t base = ((size_t)(b * Nn + i0)) * Hd + t;
    O[base + 0 * Hd] = acc0 * invs[0 * 4 + h] + X[base + 0 * Hd];
    O[base + 1 * Hd] = acc1 * invs[1 * 4 + h] + X[base + 1 * Hd];
    O[base + 2 * Hd] = acc2 * invs[2 * 4 + h] + X[base + 2 * Hd];
    O[base + 3 * Hd] = acc3 * invs[3 * 4 + h] + X[base + 3 * Hd];
}

// ---------------------------------------------------------------------------
// LayerNorm over last dim (256): out = LN(A [+ Badd]) * g + b
// grid: Mrows blocks, 256 threads
// ---------------------------------------------------------------------------
__global__ void ln_kernel(const float* __restrict__ A,
                          const float* __restrict__ Badd,
                          const float* __restrict__ gamma,
                          const float* __restrict__ beta,
                          float* __restrict__ out)
{
    __shared__ float red[256];
    int row = blockIdx.x;
    int t   = threadIdx.x;
    size_t idx = (size_t)row * Hd + t;
    float v = A[idx];
    if (Badd) v += Badd[idx];

    red[t] = v;
    __syncthreads();
#pragma unroll
    for (int off = 128; off > 0; off >>= 1) {
        if (t < off) red[t] += red[t + off];
        __syncthreads();
    }
    float mean = red[0] * (1.f / Hd);
    __syncthreads();

    float d = v - mean;
    red[t] = d * d;
    __syncthreads();
#pragma unroll
    for (int off = 128; off > 0; off >>= 1) {
        if (t < off) red[t] += red[t + off];
        __syncthreads();
    }
    float var = red[0] * (1.f / Hd);
    out[idx] = d * rsqrtf(var + 1e-5f) * gamma[t] + beta[t];
}

// ---------------------------------------------------------------------------
__global__ void fill_tail_kernel(float* __restrict__ out, int start, int total)
{
    int i = blockIdx.x * blockDim.x + threadIdx.x + start;
    if (i < total) out[i] = 1.0f;
}

// ---------------------------------------------------------------------------
extern "C" void kernel_launch(void* const* d_in, const int* in_sizes, int n_in,
                              void* d_out, int out_size)
{
    const int*   ents      = (const int*)  d_in[0];
    const int*   rels      = (const int*)  d_in[1];
    const int*   adjs      = (const int*)  d_in[2];
    const float* ent_table = (const float*)d_in[3];
    const float* rel_table = (const float*)d_in[4];
    const float* Wq        = (const float*)d_in[5];
    const float* Wk        = (const float*)d_in[6];
    const float* Wv        = (const float*)d_in[7];
    const float* l1w       = (const float*)d_in[8];
    const float* l1b       = (const float*)d_in[9];
    const float* l2w       = (const float*)d_in[10];
    const float* l2b       = (const float*)d_in[11];
    const float* ln_g      = (const float*)d_in[12];
    const float* ln_b      = (const float*)d_in[13];
    const float* alpha     = (const float*)d_in[14];
    float* out = (float*)d_out;

    float *x, *q, *k, *v, *o, *tb, *h1, *h2;
    cudaGetSymbolAddress((void**)&x,  g_x);
    cudaGetSymbolAddress((void**)&q,  g_q);
    cudaGetSymbolAddress((void**)&k,  g_k);
    cudaGetSymbolAddress((void**)&v,  g_v);
    cudaGetSymbolAddress((void**)&o,  g_o);
    cudaGetSymbolAddress((void**)&tb, g_t);
    cudaGetSymbolAddress((void**)&h1, g_h1);
    cudaGetSymbolAddress((void**)&h2, g_h2);

    cudaFuncSetAttribute(attn_kernel, cudaFuncAttributeMaxDynamicSharedMemorySize,
                         (int)ATTN_SMEM);

    embed_kernel<<<Bsz * Nn, 256>>>(ents, rels, ent_table, rel_table, x);

    for (int j = 0; j < 2; j++) {
        const float* wq = Wq  + (size_t)j * Hd * Hd;
        const float* wk = Wk  + (size_t)j * Hd * Hd;
        const float* wv = Wv  + (size_t)j * Hd * Hd;
        const float* w1 = l1w + (size_t)j * Hd * 4 * Hd;
        const float* b1 = l1b + (size_t)j * 4 * Hd;
        const float* w2 = l2w + (size_t)j * 4 * Hd * Hd;
        const float* b2 = l2b + (size_t)j * Hd;
        const float* lg = ln_g + (size_t)j * Hd;
        const float* lb = ln_b + (size_t)j * Hd;
        const float* al = alpha + (size_t)j * 4 * Hd;

        gemm_kernel<<<dim3(Hd / 64, Mrows / 64), 256>>>(x, wq, q, Mrows, Hd, Hd, nullptr, nullptr, 0);
        gemm_kernel<<<dim3(Hd / 64, Mrows / 64), 256>>>(x, wk, k, Mrows, Hd, Hd, nullptr, nullptr, 0);
        gemm_kernel<<<dim3(Hd / 64, Mrows / 64), 256>>>(x, wv, v, Mrows, Hd, Hd, nullptr, nullptr, 0);

        attn_kernel<<<dim3(Nn / 4, Bsz), 256, ATTN_SMEM>>>(q, k, v, x, adjs, o);

        ln_kernel<<<Mrows, 256>>>(o, nullptr, lg, lb, tb);

        gemm_kernel<<<dim3(4 * Hd / 64, Mrows / 64), 256>>>(tb, w1, h1, Mrows, Hd, 4 * Hd, b1, al, 1);
        gemm_kernel<<<dim3(Hd / 64, Mrows / 64), 256>>>(h1, w2, h2, Mrows, 4 * Hd, Hd, b2, nullptr, 2);

        float* dst = (j == 1) ? out : x;
        ln_kernel<<<Mrows, 256>>>(h2, tb, lg, lb, dst);
    }

    int tail = out_size - XSZ;
    if (tail > 0)
        fill_tail_kernel<<<(tail + 255) / 256, 256>>>(out, XSZ, out_size);
}

// round 3
// speedup vs baseline: 4.1477x; 4.1477x over previous
#include <cuda_runtime.h>
#include <cuda_bf16.h>

// ---------------------------------------------------------------------------
// graph_encoder: B=16, N=1024, H=256, 4 heads (d=64), 2 layers. fp32.
// R2: attention restructured as batched GEMMs (scores / softmax / AV).
// ---------------------------------------------------------------------------

#define Bsz   16
#define Nn    1024
#define Hd    256
#define Ee    767
#define Rr    256
#define ROOTI 46
#define Mrows (Bsz * Nn)            // 16384
#define XSZ   (Mrows * Hd)          // 4,194,304
#define H1SZ  (Mrows * 4 * Hd)      // 16,777,216
#define SSZ   ((size_t)Bsz * 4 * Nn * Nn)   // 67,108,864 floats (256MB)

// scratch (device globals: no allocation allowed)
__device__ float g_x [XSZ];
__device__ float g_q [XSZ];
__device__ float g_k [XSZ];
__device__ float g_kt[XSZ];     // K transposed per batch: [B,256,1024]
__device__ float g_v [XSZ];
__device__ float g_o [XSZ];
__device__ float g_t [XSZ];
__device__ float g_h2[XSZ];
__device__ float g_h1[H1SZ];
__device__ float g_s [SSZ];     // attention scores [B,4,N,N]

// ---------------------------------------------------------------------------
// Embedding gather
// ---------------------------------------------------------------------------
__global__ void embed_kernel(const int* __restrict__ ents,
                             const int* __restrict__ rels,
                             const float* __restrict__ ent_table,
                             const float* __restrict__ rel_table,
                             float* __restrict__ x)
{
    int bn = blockIdx.x;
    int b  = bn >> 10;
    int n  = bn & 1023;
    const float* src;
    if (n < Ee)            src = ent_table + (size_t)ents[b * Ee + n] * Hd;
    else if (n < Ee + Rr)  src = rel_table + (size_t)rels[b * Rr + (n - Ee)] * Hd;
    else                   src = rel_table + (size_t)ROOTI * Hd;
    x[(size_t)bn * Hd + threadIdx.x] = src[threadIdx.x];
}

// ---------------------------------------------------------------------------
// Generic tiled fp32 GEMM: C[M,Nc] = A[M,K] @ W[K,Nc] (+ bias, + PReLU)
// 64x64 tile, TK=16, 256 threads, 4x4 per-thread microtile.
// ---------------------------------------------------------------------------
__global__ void gemm_kernel(const float* __restrict__ A,
                            const float* __restrict__ W,
                            float* __restrict__ C,
                            int M, int K, int Nc,
                            const float* __restrict__ bias,
                            const float* __restrict__ alpha,
                            int mode)
{
    __shared__ float As[16][64];
    __shared__ float Bs[16][64];

    int t  = threadIdx.x;
    int tx = t & 15;
    int ty = t >> 4;
    int row0 = blockIdx.y << 6;
    int col0 = blockIdx.x << 6;

    float acc[4][4] = {};

    const float* Ap = A + (size_t)row0 * K;
    const float* Wp = W + col0;

    for (int k0 = 0; k0 < K; k0 += 16) {
#pragma unroll
        for (int i = 0; i < 4; i++) {
            int idx = t + i * 256;
            int m  = idx >> 4;
            int kk = idx & 15;
            As[kk][m] = Ap[(size_t)m * K + k0 + kk];
        }
#pragma unroll
        for (int i = 0; i < 4; i++) {
            int idx = t + i * 256;
            int kk = idx >> 6;
            int n  = idx & 63;
            Bs[kk][n] = Wp[(size_t)(k0 + kk) * Nc + n];
        }
        __syncthreads();
#pragma unroll
        for (int kk = 0; kk < 16; kk++) {
            float a0 = As[kk][ty * 4 + 0];
            float a1 = As[kk][ty * 4 + 1];
            float a2 = As[kk][ty * 4 + 2];
            float a3 = As[kk][ty * 4 + 3];
            float4 bv = *(const float4*)&Bs[kk][tx * 4];
            acc[0][0] += a0 * bv.x; acc[0][1] += a0 * bv.y; acc[0][2] += a0 * bv.z; acc[0][3] += a0 * bv.w;
            acc[1][0] += a1 * bv.x; acc[1][1] += a1 * bv.y; acc[1][2] += a1 * bv.z; acc[1][3] += a1 * bv.w;
            acc[2][0] += a2 * bv.x; acc[2][1] += a2 * bv.y; acc[2][2] += a2 * bv.z; acc[2][3] += a2 * bv.w;
            acc[3][0] += a3 * bv.x; acc[3][1] += a3 * bv.y; acc[3][2] += a3 * bv.z; acc[3][3] += a3 * bv.w;
        }
        __syncthreads();
    }

#pragma unroll
    for (int u = 0; u < 4; u++) {
        int r = row0 + ty * 4 + u;
#pragma unroll
        for (int v = 0; v < 4; v++) {
            int c = col0 + tx * 4 + v;
            float val = acc[u][v];
            if (mode != 0) val += bias[c];
            if (mode == 1) val = (val >= 0.f) ? val : alpha[c] * val;
            C[(size_t)r * Nc + c] = val;
        }
    }
}

// ---------------------------------------------------------------------------
// K transpose per batch: Kt[b, c, j] = K[b, j, c]   (c = h*64+d)
// block (32,8), grid (Hd/32, Nn/32, B)
// ---------------------------------------------------------------------------
__global__ void ktrans_kernel(const float* __restrict__ K, float* __restrict__ Kt)
{
    __shared__ float tile[32][33];
    int b  = blockIdx.z;
    int j0 = blockIdx.y << 5;
    int c0 = blockIdx.x << 5;
    int tx = threadIdx.x;
    int ty = threadIdx.y;
    const float* src = K + (size_t)b * Nn * Hd;
#pragma unroll
    for (int r = ty; r < 32; r += 8)
        tile[r][tx] = src[(size_t)(j0 + r) * Hd + c0 + tx];
    __syncthreads();
    float* dst = Kt + (size_t)b * Hd * Nn;
#pragma unroll
    for (int r = ty; r < 32; r += 8)
        dst[(size_t)(c0 + r) * Nn + j0 + tx] = tile[tx][r];
}

// ---------------------------------------------------------------------------
// Scores batched GEMM: S[b,h,i,j] = (Q_h[i,:] . K_h[j,:]) / 16, masked.
// Per block: 64x64 output tile of one (b,h). K-dim = 64.
// grid (Nn/64, Nn/64, B*4), 256 threads.
// ---------------------------------------------------------------------------
__global__ void score_kernel(const float* __restrict__ Q,   // [B,N,256]
                             const float* __restrict__ Kt,  // [B,256,N]
                             const int* __restrict__ adj,   // [B,N,N]
                             float* __restrict__ S)         // [B,4,N,N]
{
    __shared__ float As[16][64];
    __shared__ float Bs[16][64];

    int t  = threadIdx.x;
    int tx = t & 15;
    int ty = t >> 4;
    int z  = blockIdx.z;        // b*4 + h
    int b  = z >> 2;
    int h  = z & 3;
    int i0 = blockIdx.y << 6;
    int j0 = blockIdx.x << 6;

    const float* Ap = Q  + ((size_t)(b * Nn + i0)) * Hd + h * 64;      // lda=256
    const float* Bp = Kt + ((size_t)b * Hd + h * 64) * Nn + j0;        // ldb=1024

    float acc[4][4] = {};

    for (int k0 = 0; k0 < 64; k0 += 16) {
#pragma unroll
        for (int i = 0; i < 4; i++) {
            int idx = t + i * 256;
            int m  = idx >> 4;
            int kk = idx & 15;
            As[kk][m] = Ap[(size_t)m * Hd + k0 + kk];
        }
#pragma unroll
        for (int i = 0; i < 4; i++) {
            int idx = t + i * 256;
            int kk = idx >> 6;
            int n  = idx & 63;
            Bs[kk][n] = Bp[(size_t)(k0 + kk) * Nn + n];
        }
        __syncthreads();
#pragma unroll
        for (int kk = 0; kk < 16; kk++) {
            float a0 = As[kk][ty * 4 + 0];
            float a1 = As[kk][ty * 4 + 1];
            float a2 = As[kk][ty * 4 + 2];
            float a3 = As[kk][ty * 4 + 3];
            float4 bv = *(const float4*)&Bs[kk][tx * 4];
            acc[0][0] += a0 * bv.x; acc[0][1] += a0 * bv.y; acc[0][2] += a0 * bv.z; acc[0][3] += a0 * bv.w;
            acc[1][0] += a1 * bv.x; acc[1][1] += a1 * bv.y; acc[1][2] += a1 * bv.z; acc[1][3] += a1 * bv.w;
            acc[2][0] += a2 * bv.x; acc[2][1] += a2 * bv.y; acc[2][2] += a2 * bv.z; acc[2][3] += a2 * bv.w;
            acc[3][0] += a3 * bv.x; acc[3][1] += a3 * bv.y; acc[3][2] += a3 * bv.z; acc[3][3] += a3 * bv.w;
        }
        __syncthreads();
    }

    float* Sz = S + ((size_t)z << 20);
#pragma unroll
    for (int u = 0; u < 4; u++) {
        int r = i0 + ty * 4 + u;
        const int* arow = adj + ((size_t)(b * Nn + r) << 10);
#pragma unroll
        for (int v = 0; v < 4; v++) {
            int c = j0 + tx * 4 + v;
            Sz[((size_t)r << 10) + c] = arow[c] ? acc[u][v] * 0.0625f : -1e30f;
        }
    }
}

// ---------------------------------------------------------------------------
// Row softmax over S: one block per row (1024 elements), 256 threads.
// grid = B*4*N = 65536
// ---------------------------------------------------------------------------
__global__ void softmax_kernel(float* __restrict__ S)
{
    __shared__ float red[256];
    int t = threadIdx.x;
    float4* p = (float4*)(S + ((size_t)blockIdx.x << 10));
    float4 v = p[t];

    float mx = fmaxf(fmaxf(v.x, v.y), fmaxf(v.z, v.w));
    red[t] = mx;
    __syncthreads();
#pragma unroll
    for (int off = 128; off > 0; off >>= 1) {
        if (t < off) red[t] = fmaxf(red[t], red[t + off]);
        __syncthreads();
    }
    mx = red[0];
    __syncthreads();

    v.x = __expf(v.x - mx);
    v.y = __expf(v.y - mx);
    v.z = __expf(v.z - mx);
    v.w = __expf(v.w - mx);
    red[t] = v.x + v.y + v.z + v.w;
    __syncthreads();
#pragma unroll
    for (int off = 128; off > 0; off >>= 1) {
        if (t < off) red[t] += red[t + off];
        __syncthreads();
    }
    float inv = 1.f / red[0];
    v.x *= inv; v.y *= inv; v.z *= inv; v.w *= inv;
    p[t] = v;
}

// ---------------------------------------------------------------------------
// AV batched GEMM: O[b,i,h*64+c] = sum_j S[b,h,i,j] * V[b,j,h*64+c] + X
// Per block: 64 rows x 64 cols (full head dim) of one (b,h). K = 1024.
// grid (Nn/64, B*4), 256 threads.
// ---------------------------------------------------------------------------
__global__ void av_kernel(const float* __restrict__ S,  // [B,4,N,N] normalized
                          const float* __restrict__ V,  // [B,N,256]
                          const float* __restrict__ X,
                          float* __restrict__ O)
{
    __shared__ float As[16][64];
    __shared__ float Bs[16][64];

    int t  = threadIdx.x;
    int tx = t & 15;
    int ty = t >> 4;
    int z  = blockIdx.y;        // b*4 + h
    int b  = z >> 2;
    int h  = z & 3;
    int i0 = blockIdx.x << 6;

    const float* Ap = S + ((size_t)z << 20) + ((size_t)i0 << 10);  // lda=1024
    const float* Bp = V + ((size_t)b * Nn) * Hd + h * 64;          // ldb=256

    float acc[4][4] = {};

    for (int k0 = 0; k0 < Nn; k0 += 16) {
#pragma unroll
        for (int i = 0; i < 4; i++) {
            int idx = t + i * 256;
            int m  = idx >> 4;
            int kk = idx & 15;
            As[kk][m] = Ap[((size_t)m << 10) + k0 + kk];
        }
#pragma unroll
        for (int i = 0; i < 4; i++) {
            int idx = t + i * 256;
            int kk = idx >> 6;
            int n  = idx & 63;
            Bs[kk][n] = Bp[(size_t)(k0 + kk) * Hd + n];
        }
        __syncthreads();
#pragma unroll
        for (int kk = 0; kk < 16; kk++) {
            float a0 = As[kk][ty * 4 + 0];
            float a1 = As[kk][ty * 4 + 1];
            float a2 = As[kk][ty * 4 + 2];
            float a3 = As[kk][ty * 4 + 3];
            float4 bv = *(const float4*)&Bs[kk][tx * 4];
            acc[0][0] += a0 * bv.x; acc[0][1] += a0 * bv.y; acc[0][2] += a0 * bv.z; acc[0][3] += a0 * bv.w;
            acc[1][0] += a1 * bv.x; acc[1][1] += a1 * bv.y; acc[1][2] += a1 * bv.z; acc[1][3] += a1 * bv.w;
            acc[2][0] += a2 * bv.x; acc[2][1] += a2 * bv.y; acc[2][2] += a2 * bv.z; acc[2][3] += a2 * bv.w;
            acc[3][0] += a3 * bv.x; acc[3][1] += a3 * bv.y; acc[3][2] += a3 * bv.z; acc[3][3] += a3 * bv.w;
        }
        __syncthreads();
    }

#pragma unroll
    for (int u = 0; u < 4; u++) {
        int r = i0 + ty * 4 + u;
#pragma unroll
        for (int v = 0; v < 4; v++) {
            int c = tx * 4 + v;
            size_t idx = ((size_t)(b * Nn + r)) * Hd + h * 64 + c;
            O[idx] = acc[u][v] + X[idx];
        }
    }
}

// ---------------------------------------------------------------------------
// LayerNorm over last dim (256): out = LN(A [+ Badd]) * g + b
// ---------------------------------------------------------------------------
__global__ void ln_kernel(const float* __restrict__ A,
                          const float* __restrict__ Badd,
                          const float* __restrict__ gamma,
                          const float* __restrict__ beta,
                          float* __restrict__ out)
{
    __shared__ float red[256];
    int row = blockIdx.x;
    int t   = threadIdx.x;
    size_t idx = (size_t)row * Hd + t;
    float v = A[idx];
    if (Badd) v += Badd[idx];

    red[t] = v;
    __syncthreads();
#pragma unroll
    for (int off = 128; off > 0; off >>= 1) {
        if (t < off) red[t] += red[t + off];
        __syncthreads();
    }
    float mean = red[0] * (1.f / Hd);
    __syncthreads();

    float d = v - mean;
    red[t] = d * d;
    __syncthreads();
#pragma unroll
    for (int off = 128; off > 0; off >>= 1) {
        if (t < off) red[t] += red[t + off];
        __syncthreads();
    }
    float var = red[0] * (1.f / Hd);
    out[idx] = d * rsqrtf(var + 1e-5f) * gamma[t] + beta[t];
}

// ---------------------------------------------------------------------------
__global__ void fill_tail_kernel(float* __restrict__ out, int start, int total)
{
    int i = blockIdx.x * blockDim.x + threadIdx.x + start;
    if (i < total) out[i] = 1.0f;
}

// ---------------------------------------------------------------------------
extern "C" void kernel_launch(void* const* d_in, const int* in_sizes, int n_in,
                              void* d_out, int out_size)
{
    const int*   ents      = (const int*)  d_in[0];
    const int*   rels      = (const int*)  d_in[1];
    const int*   adjs      = (const int*)  d_in[2];
    const float* ent_table = (const float*)d_in[3];
    const float* rel_table = (const float*)d_in[4];
    const float* Wq        = (const float*)d_in[5];
    const float* Wk        = (const float*)d_in[6];
    const float* Wv        = (const float*)d_in[7];
    const float* l1w       = (const float*)d_in[8];
    const float* l1b       = (const float*)d_in[9];
    const float* l2w       = (const float*)d_in[10];
    const float* l2b       = (const float*)d_in[11];
    const float* ln_g      = (const float*)d_in[12];
    const float* ln_b      = (const float*)d_in[13];
    const float* alpha     = (const float*)d_in[14];
    float* out = (float*)d_out;

    float *x, *q, *k, *kt, *v, *o, *tb, *h1, *h2, *s;
    cudaGetSymbolAddress((void**)&x,  g_x);
    cudaGetSymbolAddress((void**)&q,  g_q);
    cudaGetSymbolAddress((void**)&k,  g_k);
    cudaGetSymbolAddress((void**)&kt, g_kt);
    cudaGetSymbolAddress((void**)&v,  g_v);
    cudaGetSymbolAddress((void**)&o,  g_o);
    cudaGetSymbolAddress((void**)&tb, g_t);
    cudaGetSymbolAddress((void**)&h1, g_h1);
    cudaGetSymbolAddress((void**)&h2, g_h2);
    cudaGetSymbolAddress((void**)&s,  g_s);

    embed_kernel<<<Bsz * Nn, 256>>>(ents, rels, ent_table, rel_table, x);

    for (int j = 0; j < 2; j++) {
        const float* wq = Wq  + (size_t)j * Hd * Hd;
        const float* wk = Wk  + (size_t)j * Hd * Hd;
        const float* wv = Wv  + (size_t)j * Hd * Hd;
        const float* w1 = l1w + (size_t)j * Hd * 4 * Hd;
        const float* b1 = l1b + (size_t)j * 4 * Hd;
        const float* w2 = l2w + (size_t)j * 4 * Hd * Hd;
        const float* b2 = l2b + (size_t)j * Hd;
        const float* lg = ln_g + (size_t)j * Hd;
        const float* lb = ln_b + (size_t)j * Hd;
        const float* al = alpha + (size_t)j * 4 * Hd;

        gemm_kernel<<<dim3(Hd / 64, Mrows / 64), 256>>>(x, wq, q, Mrows, Hd, Hd, nullptr, nullptr, 0);
        gemm_kernel<<<dim3(Hd / 64, Mrows / 64), 256>>>(x, wk, k, Mrows, Hd, Hd, nullptr, nullptr, 0);
        gemm_kernel<<<dim3(Hd / 64, Mrows / 64), 256>>>(x, wv, v, Mrows, Hd, Hd, nullptr, nullptr, 0);

        ktrans_kernel<<<dim3(Hd / 32, Nn / 32, Bsz), dim3(32, 8)>>>(k, kt);

        score_kernel<<<dim3(Nn / 64, Nn / 64, Bsz * 4), 256>>>(q, kt, adjs, s);
        softmax_kernel<<<Bsz * 4 * Nn, 256>>>(s);
        av_kernel<<<dim3(Nn / 64, Bsz * 4), 256>>>(s, v, x, o);

        ln_kernel<<<Mrows, 256>>>(o, nullptr, lg, lb, tb);

        gemm_kernel<<<dim3(4 * Hd / 64, Mrows / 64), 256>>>(tb, w1, h1, Mrows, Hd, 4 * Hd, b1, al, 1);
        gemm_kernel<<<dim3(Hd / 64, Mrows / 64), 256>>>(h1, w2, h2, Mrows, 4 * Hd, Hd, b2, nullptr, 2);

        float* dst = (j == 1) ? out : x;
        ln_kernel<<<Mrows, 256>>>(h2, tb, lg, lb, dst);
    }

    int tail = out_size - XSZ;
    if (tail > 0)
        fill_tail_kernel<<<(tail + 255) / 256, 256>>>(out, XSZ, out_size);
}

// round 4
// speedup vs baseline: 7.1339x; 1.7200x over previous
#include <cuda_runtime.h>
#include <cuda_bf16.h>

// ---------------------------------------------------------------------------
// graph_encoder: B=16, N=1024, H=256, 4 heads (d=64), 2 layers. fp32.
// R3: 128x128 double-buffered SGEMM, fused QKV, softmax fused into AV.
// ---------------------------------------------------------------------------

#define Bsz   16
#define Nn    1024
#define Hd    256
#define Ee    767
#define Rr    256
#define ROOTI 46
#define Mrows (Bsz * Nn)                    // 16384
#define XSZ   (Mrows * Hd)                  // 4,194,304
#define H1SZ  (Mrows * 4 * Hd)              // 16,777,216
#define QKVSZ (Mrows * 3 * Hd)              // 12,582,912
#define SSZ   ((size_t)Bsz * 4 * Nn * Nn)   // 67,108,864 floats
#define NROWS (Bsz * 4 * Nn)                // 65536 score rows

__device__ float g_x   [XSZ];
__device__ float g_qkv [QKVSZ];   // [16384, 768]  (q | k | v)
__device__ float g_kt  [XSZ];     // [B, 256, 1024]
__device__ float g_o   [XSZ];
__device__ float g_t   [XSZ];
__device__ float g_h2  [XSZ];
__device__ float g_h1  [H1SZ];
__device__ float g_s   [SSZ];     // scores [B,4,N,N] (masked, scaled)
__device__ float g_rmax[NROWS];
__device__ float g_rinv[NROWS];
__device__ float g_wqkv[Hd * 3 * Hd];  // packed [256,768]

// ---------------------------------------------------------------------------
__global__ void embed_kernel(const int* __restrict__ ents,
                             const int* __restrict__ rels,
                             const float* __restrict__ ent_table,
                             const float* __restrict__ rel_table,
                             float* __restrict__ x)
{
    int bn = blockIdx.x;
    int b  = bn >> 10;
    int n  = bn & 1023;
    const float* src;
    if (n < Ee)            src = ent_table + (size_t)ents[b * Ee + n] * Hd;
    else if (n < Ee + Rr)  src = rel_table + (size_t)rels[b * Rr + (n - Ee)] * Hd;
    else                   src = rel_table + (size_t)ROOTI * Hd;
    x[(size_t)bn * Hd + threadIdx.x] = src[threadIdx.x];
}

// ---------------------------------------------------------------------------
__global__ void packw_kernel(const float* __restrict__ wq,
                             const float* __restrict__ wk,
                             const float* __restrict__ wv,
                             float* __restrict__ out)
{
    int i = blockIdx.x * blockDim.x + threadIdx.x;   // 0..196607
    int k = i / 768, c = i - k * 768;
    float v;
    if (c < 256)      v = wq[k * 256 + c];
    else if (c < 512) v = wk[k * 256 + c - 256];
    else              v = wv[k * 256 + c - 512];
    out[i] = v;
}

// ---------------------------------------------------------------------------
// 128x128 double-buffered SGEMM. 256 threads, 8x8 strided microtile.
// C[M,Nc] = A @ W, with lda/ldb/ldc. mode: 0 plain, 1 bias+PReLU, 2 bias.
// ---------------------------------------------------------------------------
__global__ void __launch_bounds__(256, 2)
gemm128_kernel(const float* __restrict__ A,
               const float* __restrict__ W,
               float* __restrict__ C,
               int K, int lda, int ldb, int ldc,
               const float* __restrict__ bias,
               const float* __restrict__ alpha,
               int mode)
{
    __shared__ float As[2][8][128];
    __shared__ float Bs[2][8][128];

    int t  = threadIdx.x;
    int tx = t & 15, ty = t >> 4;
    int tx4 = tx * 4, ty4 = ty * 4;
    int row0 = blockIdx.y << 7;
    int col0 = blockIdx.x << 7;

    int ar = t >> 1;            // 0..127
    int ac = (t & 1) * 4;       // 0 / 4
    int bkk = t >> 5;           // 0..7
    int bc  = (t & 31) * 4;

    const float* Aptr = A + (size_t)(row0 + ar) * lda + ac;
    const float* Bptr = W + (size_t)bkk * ldb + col0 + bc;

    float4 a = *(const float4*)Aptr;
    float4 b = *(const float4*)Bptr;
    As[0][ac + 0][ar] = a.x; As[0][ac + 1][ar] = a.y;
    As[0][ac + 2][ar] = a.z; As[0][ac + 3][ar] = a.w;
    *(float4*)&Bs[0][bkk][bc] = b;
    __syncthreads();

    float acc[8][8] = {};
    int buf = 0;

    for (int k0 = 8; k0 <= K; k0 += 8) {
        float4 an, bn;
        if (k0 < K) {
            an = *(const float4*)(Aptr + k0);
            bn = *(const float4*)(Bptr + (size_t)k0 * ldb);
        }
#pragma unroll
        for (int kk = 0; kk < 8; kk++) {
            float4 a0 = *(const float4*)&As[buf][kk][ty4];
            float4 a1 = *(const float4*)&As[buf][kk][ty4 + 64];
            float4 b0 = *(const float4*)&Bs[buf][kk][tx4];
            float4 b1 = *(const float4*)&Bs[buf][kk][tx4 + 64];
            float av_[8] = {a0.x, a0.y, a0.z, a0.w, a1.x, a1.y, a1.z, a1.w};
            float bv_[8] = {b0.x, b0.y, b0.z, b0.w, b1.x, b1.y, b1.z, b1.w};
#pragma unroll
            for (int u = 0; u < 8; u++)
#pragma unroll
                for (int v = 0; v < 8; v++)
                    acc[u][v] += av_[u] * bv_[v];
        }
        if (k0 < K) {
            buf ^= 1;
            As[buf][ac + 0][ar] = an.x; As[buf][ac + 1][ar] = an.y;
            As[buf][ac + 2][ar] = an.z; As[buf][ac + 3][ar] = an.w;
            *(float4*)&Bs[buf][bkk][bc] = bn;
            __syncthreads();
        }
    }

#pragma unroll
    for (int gr = 0; gr < 2; gr++)
#pragma unroll
    for (int u = 0; u < 4; u++) {
        int r = row0 + gr * 64 + ty4 + u;
#pragma unroll
        for (int gc = 0; gc < 2; gc++) {
            int c = col0 + gc * 64 + tx4;
            float4 o;
            o.x = acc[gr * 4 + u][gc * 4 + 0];
            o.y = acc[gr * 4 + u][gc * 4 + 1];
            o.z = acc[gr * 4 + u][gc * 4 + 2];
            o.w = acc[gr * 4 + u][gc * 4 + 3];
            if (mode != 0) {
                o.x += bias[c + 0]; o.y += bias[c + 1];
                o.z += bias[c + 2]; o.w += bias[c + 3];
            }
            if (mode == 1) {
                o.x = o.x >= 0.f ? o.x : alpha[c + 0] * o.x;
                o.y = o.y >= 0.f ? o.y : alpha[c + 1] * o.y;
                o.z = o.z >= 0.f ? o.z : alpha[c + 2] * o.z;
                o.w = o.w >= 0.f ? o.w : alpha[c + 3] * o.w;
            }
            *(float4*)&C[(size_t)r * ldc + c] = o;
        }
    }
}

// ---------------------------------------------------------------------------
// K transpose per batch from packed qkv: Kt[b,c,j] = qkv[b*N+j, 256+c]
// ---------------------------------------------------------------------------
__global__ void ktrans_kernel(const float* __restrict__ qkv, float* __restrict__ Kt)
{
    __shared__ float tile[32][33];
    int b  = blockIdx.z;
    int j0 = blockIdx.y << 5;
    int c0 = blockIdx.x << 5;
    int tx = threadIdx.x;
    int ty = threadIdx.y;
    const float* src = qkv + (size_t)b * Nn * 768 + 256;
#pragma unroll
    for (int r = ty; r < 32; r += 8)
        tile[r][tx] = src[(size_t)(j0 + r) * 768 + c0 + tx];
    __syncthreads();
    float* dst = Kt + (size_t)b * Hd * Nn;
#pragma unroll
    for (int r = ty; r < 32; r += 8)
        dst[(size_t)(c0 + r) * Nn + j0 + tx] = tile[tx][r];
}

// ---------------------------------------------------------------------------
// Score: per (b,h) 128x128 tile, K=64. A = Q section of qkv, B = Kt.
// Epilogue: scale 1/16 + adjacency mask -> S.
// grid (8, 8, 64)
// ---------------------------------------------------------------------------
__global__ void __launch_bounds__(256, 2)
score_kernel(const float* __restrict__ qkv,
             const float* __restrict__ Kt,
             const int* __restrict__ adj,
             float* __restrict__ S)
{
    __shared__ float As[2][8][128];
    __shared__ float Bs[2][8][128];

    int t  = threadIdx.x;
    int tx = t & 15, ty = t >> 4;
    int tx4 = tx * 4, ty4 = ty * 4;
    int z = blockIdx.z;
    int b = z >> 2, h = z & 3;
    int i0 = blockIdx.y << 7;
    int j0 = blockIdx.x << 7;

    int ar = t >> 1;
    int ac = (t & 1) * 4;
    int bkk = t >> 5;
    int bc  = (t & 31) * 4;

    const float* Aptr = qkv + (size_t)(b * Nn + i0 + ar) * 768 + h * 64 + ac;
    const float* Bptr = Kt + ((size_t)b * Hd + h * 64 + bkk) * Nn + j0 + bc;

    float4 a = *(const float4*)Aptr;
    float4 bb = *(const float4*)Bptr;
    As[0][ac + 0][ar] = a.x; As[0][ac + 1][ar] = a.y;
    As[0][ac + 2][ar] = a.z; As[0][ac + 3][ar] = a.w;
    *(float4*)&Bs[0][bkk][bc] = bb;
    __syncthreads();

    float acc[8][8] = {};
    int buf = 0;

    for (int k0 = 8; k0 <= 64; k0 += 8) {
        float4 an, bn;
        if (k0 < 64) {
            an = *(const float4*)(Aptr + k0);
            bn = *(const float4*)(Bptr + (size_t)k0 * Nn);
        }
#pragma unroll
        for (int kk = 0; kk < 8; kk++) {
            float4 a0 = *(const float4*)&As[buf][kk][ty4];
            float4 a1 = *(const float4*)&As[buf][kk][ty4 + 64];
            float4 b0 = *(const float4*)&Bs[buf][kk][tx4];
            float4 b1 = *(const float4*)&Bs[buf][kk][tx4 + 64];
            float av_[8] = {a0.x, a0.y, a0.z, a0.w, a1.x, a1.y, a1.z, a1.w};
            float bv_[8] = {b0.x, b0.y, b0.z, b0.w, b1.x, b1.y, b1.z, b1.w};
#pragma unroll
            for (int u = 0; u < 8; u++)
#pragma unroll
                for (int v = 0; v < 8; v++)
                    acc[u][v] += av_[u] * bv_[v];
        }
        if (k0 < 64) {
            buf ^= 1;
            As[buf][ac + 0][ar] = an.x; As[buf][ac + 1][ar] = an.y;
            As[buf][ac + 2][ar] = an.z; As[buf][ac + 3][ar] = an.w;
            *(float4*)&Bs[buf][bkk][bc] = bn;
            __syncthreads();
        }
    }

    float* Sz = S + ((size_t)z << 20);
#pragma unroll
    for (int gr = 0; gr < 2; gr++)
#pragma unroll
    for (int u = 0; u < 4; u++) {
        int r = i0 + gr * 64 + ty4 + u;
        const int* arow = adj + ((size_t)(b * Nn + r) << 10);
#pragma unroll
        for (int gc = 0; gc < 2; gc++) {
            int c = j0 + gc * 64 + tx4;
            int4 m = *(const int4*)&arow[c];
            float4 o;
            o.x = m.x ? acc[gr * 4 + u][gc * 4 + 0] * 0.0625f : -1e30f;
            o.y = m.y ? acc[gr * 4 + u][gc * 4 + 1] * 0.0625f : -1e30f;
            o.z = m.z ? acc[gr * 4 + u][gc * 4 + 2] * 0.0625f : -1e30f;
            o.w = m.w ? acc[gr * 4 + u][gc * 4 + 3] * 0.0625f : -1e30f;
            *(float4*)&Sz[((size_t)r << 10) + c] = o;
        }
    }
}

// ---------------------------------------------------------------------------
// Row stats: per row of S compute max and 1/sum(exp). grid = 65536.
// ---------------------------------------------------------------------------
__global__ void rowstat_kernel(const float* __restrict__ S,
                               float* __restrict__ rmax,
                               float* __restrict__ rinv)
{
    __shared__ float red[256];
    int t = threadIdx.x;
    const float4* p = (const float4*)(S + ((size_t)blockIdx.x << 10));
    float4 v = p[t];

    float mx = fmaxf(fmaxf(v.x, v.y), fmaxf(v.z, v.w));
    red[t] = mx;
    __syncthreads();
#pragma unroll
    for (int off = 128; off > 0; off >>= 1) {
        if (t < off) red[t] = fmaxf(red[t], red[t + off]);
        __syncthreads();
    }
    mx = red[0];
    __syncthreads();

    float s = __expf(v.x - mx) + __expf(v.y - mx)
            + __expf(v.z - mx) + __expf(v.w - mx);
    red[t] = s;
    __syncthreads();
#pragma unroll
    for (int off = 128; off > 0; off >>= 1) {
        if (t < off) red[t] += red[t + off];
        __syncthreads();
    }
    if (t == 0) {
        rmax[blockIdx.x] = mx;
        rinv[blockIdx.x] = 1.f / red[0];
    }
}

// ---------------------------------------------------------------------------
// AV: per (b,h) 128 rows x 64 cols, K=1024. A = exp(S - max)*inv on the fly.
// Epilogue adds residual X. grid (8, 64).
// ---------------------------------------------------------------------------
__global__ void __launch_bounds__(256, 2)
av_kernel(const float* __restrict__ S,
          const float* __restrict__ qkv,
          const float* __restrict__ rmax,
          const float* __restrict__ rinv,
          const float* __restrict__ X,
          float* __restrict__ O)
{
    __shared__ float As[2][8][128];
    __shared__ float Bs[2][8][64];

    int t  = threadIdx.x;
    int tx = t & 15, ty = t >> 4;
    int tx4 = tx * 4, ty4 = ty * 4;
    int z = blockIdx.y;
    int b = z >> 2, h = z & 3;
    int i0 = blockIdx.x << 7;

    int ar = t >> 1;
    int ac = (t & 1) * 4;
    int bkk = t >> 5;
    int bc  = (t & 31) * 2;

    const float* Aptr = S + ((size_t)z << 20) + ((size_t)(i0 + ar) << 10) + ac;
    const float* Bptr = qkv + (size_t)bkk * 768 + (size_t)b * Nn * 768 + 512 + h * 64 + bc;

    float rm = rmax[(z << 10) + i0 + ar];
    float ri = rinv[(z << 10) + i0 + ar];

    float4 a = *(const float4*)Aptr;
    float2 bb = *(const float2*)Bptr;
    As[0][ac + 0][ar] = __expf(a.x - rm) * ri;
    As[0][ac + 1][ar] = __expf(a.y - rm) * ri;
    As[0][ac + 2][ar] = __expf(a.z - rm) * ri;
    As[0][ac + 3][ar] = __expf(a.w - rm) * ri;
    Bs[0][bkk][bc] = bb.x; Bs[0][bkk][bc + 1] = bb.y;
    __syncthreads();

    float acc[8][4] = {};
    int buf = 0;

    for (int k0 = 8; k0 <= Nn; k0 += 8) {
        float4 an; float2 bn;
        if (k0 < Nn) {
            an = *(const float4*)(Aptr + k0);
            bn = *(const float2*)(Bptr + (size_t)k0 * 768);
        }
#pragma unroll
        for (int kk = 0; kk < 8; kk++) {
            float4 a0 = *(const float4*)&As[buf][kk][ty4];
            float4 a1 = *(const float4*)&As[buf][kk][ty4 + 64];
            float4 b0 = *(const float4*)&Bs[buf][kk][tx4];
            float av_[8] = {a0.x, a0.y, a0.z, a0.w, a1.x, a1.y, a1.z, a1.w};
            float bv_[4] = {b0.x, b0.y, b0.z, b0.w};
#pragma unroll
            for (int u = 0; u < 8; u++)
#pragma unroll
                for (int v = 0; v < 4; v++)
                    acc[u][v] += av_[u] * bv_[v];
        }
        if (k0 < Nn) {
            buf ^= 1;
            As[buf][ac + 0][ar] = __expf(an.x - rm) * ri;
            As[buf][ac + 1][ar] = __expf(an.y - rm) * ri;
            As[buf][ac + 2][ar] = __expf(an.z - rm) * ri;
            As[buf][ac + 3][ar] = __expf(an.w - rm) * ri;
            Bs[buf][bkk][bc] = bn.x; Bs[buf][bkk][bc + 1] = bn.y;
            __syncthreads();
        }
    }

#pragma unroll
    for (int gr = 0; gr < 2; gr++)
#pragma unroll
    for (int u = 0; u < 4; u++) {
        int r = i0 + gr * 64 + ty4 + u;
        size_t idx = (size_t)(b * Nn + r) * Hd + h * 64 + tx4;
        float4 xr = *(const float4*)&X[idx];
        float4 o;
        o.x = acc[gr * 4 + u][0] + xr.x;
        o.y = acc[gr * 4 + u][1] + xr.y;
        o.z = acc[gr * 4 + u][2] + xr.z;
        o.w = acc[gr * 4 + u][3] + xr.w;
        *(float4*)&O[idx] = o;
    }
}

// ---------------------------------------------------------------------------
__global__ void ln_kernel(const float* __restrict__ A,
                          const float* __restrict__ Badd,
                          const float* __restrict__ gamma,
                          const float* __restrict__ beta,
                          float* __restrict__ out)
{
    __shared__ float red[256];
    int row = blockIdx.x;
    int t   = threadIdx.x;
    size_t idx = (size_t)row * Hd + t;
    float v = A[idx];
    if (Badd) v += Badd[idx];

    red[t] = v;
    __syncthreads();
#pragma unroll
    for (int off = 128; off > 0; off >>= 1) {
        if (t < off) red[t] += red[t + off];
        __syncthreads();
    }
    float mean = red[0] * (1.f / Hd);
    __syncthreads();

    float d = v - mean;
    red[t] = d * d;
    __syncthreads();
#pragma unroll
    for (int off = 128; off > 0; off >>= 1) {
        if (t < off) red[t] += red[t + off];
        __syncthreads();
    }
    float var = red[0] * (1.f / Hd);
    out[idx] = d * rsqrtf(var + 1e-5f) * gamma[t] + beta[t];
}

// ---------------------------------------------------------------------------
__global__ void fill_tail_kernel(float* __restrict__ out, int start, int total)
{
    int i = blockIdx.x * blockDim.x + threadIdx.x + start;
    if (i < total) out[i] = 1.0f;
}

// ---------------------------------------------------------------------------
extern "C" void kernel_launch(void* const* d_in, const int* in_sizes, int n_in,
                              void* d_out, int out_size)
{
    const int*   ents      = (const int*)  d_in[0];
    const int*   rels      = (const int*)  d_in[1];
    const int*   adjs      = (const int*)  d_in[2];
    const float* ent_table = (const float*)d_in[3];
    const float* rel_table = (const float*)d_in[4];
    const float* Wq        = (const float*)d_in[5];
    const float* Wk        = (const float*)d_in[6];
    const float* Wv        = (const float*)d_in[7];
    const float* l1w       = (const float*)d_in[8];
    const float* l1b       = (const float*)d_in[9];
    const float* l2w       = (const float*)d_in[10];
    const float* l2b       = (const float*)d_in[11];
    const float* ln_g      = (const float*)d_in[12];
    const float* ln_b      = (const float*)d_in[13];
    const float* alpha     = (const float*)d_in[14];
    float* out = (float*)d_out;

    float *x, *qkv, *kt, *o, *tb, *h1, *h2, *s, *rmax, *rinv, *wqkv;
    cudaGetSymbolAddress((void**)&x,    g_x);
    cudaGetSymbolAddress((void**)&qkv,  g_qkv);
    cudaGetSymbolAddress((void**)&kt,   g_kt);
    cudaGetSymbolAddress((void**)&o,    g_o);
    cudaGetSymbolAddress((void**)&tb,   g_t);
    cudaGetSymbolAddress((void**)&h1,   g_h1);
    cudaGetSymbolAddress((void**)&h2,   g_h2);
    cudaGetSymbolAddress((void**)&s,    g_s);
    cudaGetSymbolAddress((void**)&rmax, g_rmax);
    cudaGetSymbolAddress((void**)&rinv, g_rinv);
    cudaGetSymbolAddress((void**)&wqkv, g_wqkv);

    embed_kernel<<<Bsz * Nn, 256>>>(ents, rels, ent_table, rel_table, x);

    for (int j = 0; j < 2; j++) {
        const float* wq = Wq  + (size_t)j * Hd * Hd;
        const float* wk = Wk  + (size_t)j * Hd * Hd;
        const float* wv = Wv  + (size_t)j * Hd * Hd;
        const float* w1 = l1w + (size_t)j * Hd * 4 * Hd;
        const float* b1 = l1b + (size_t)j * 4 * Hd;
        const float* w2 = l2w + (size_t)j * 4 * Hd * Hd;
        const float* b2 = l2b + (size_t)j * Hd;
        const float* lg = ln_g + (size_t)j * Hd;
        const float* lb = ln_b + (size_t)j * Hd;
        const float* al = alpha + (size_t)j * 4 * Hd;

        packw_kernel<<<768, 256>>>(wq, wk, wv, wqkv);

        // fused QKV: [16384,256] @ [256,768] -> [16384,768]
        gemm128_kernel<<<dim3(6, 128), 256>>>(x, wqkv, qkv,
                                              Hd, Hd, 768, 768,
                                              nullptr, nullptr, 0);

        ktrans_kernel<<<dim3(8, 32, Bsz), dim3(32, 8)>>>(qkv, kt);

        score_kernel<<<dim3(8, 8, Bsz * 4), 256>>>(qkv, kt, adjs, s);
        rowstat_kernel<<<NROWS, 256>>>(s, rmax, rinv);
        av_kernel<<<dim3(8, Bsz * 4), 256>>>(s, qkv, rmax, rinv, x, o);

        ln_kernel<<<Mrows, 256>>>(o, nullptr, lg, lb, tb);

        // MLP1: [16384,256] @ [256,1024], bias + PReLU
        gemm128_kernel<<<dim3(8, 128), 256>>>(tb, w1, h1,
                                              Hd, Hd, 4 * Hd, 4 * Hd,
                                              b1, al, 1);
        // MLP2: [16384,1024] @ [1024,256], bias
        gemm128_kernel<<<dim3(2, 128), 256>>>(h1, w2, h2,
                                              4 * Hd, 4 * Hd, Hd, Hd,
                                              b2, nullptr, 2);

        float* dst = (j == 1) ? out : x;
        ln_kernel<<<Mrows, 256>>>(h2, tb, lg, lb, dst);
    }

    int tail = out_size - XSZ;
    if (tail > 0)
        fill_tail_kernel<<<(tail + 255) / 256, 256>>>(out, XSZ, out_size);
}

// round 5
// speedup vs baseline: 10.1502x; 1.4228x over previous
#include <cuda_runtime.h>
#include <cuda_bf16.h>

// ---------------------------------------------------------------------------
// graph_encoder: B=16, N=1024, H=256, 4 heads (d=64), 2 layers.
// R4: tf32 mma.sync tensor-core GEMMs (fp32 accumulate) for all matmuls.
// ---------------------------------------------------------------------------

#define Bsz   16
#define Nn    1024
#define Hd    256
#define Ee    767
#define Rr    256
#define ROOTI 46
#define Mrows (Bsz * Nn)                    // 16384
#define XSZ   (Mrows * Hd)                  // 4,194,304
#define H1SZ  (Mrows * 4 * Hd)              // 16,777,216
#define QKVSZ (Mrows * 3 * Hd)
#define SSZ   ((size_t)Bsz * 4 * Nn * Nn)   // 67,108,864 floats
#define NROWS (Bsz * 4 * Nn)                // 65536

__device__ float g_x   [XSZ];
__device__ float g_qkv [QKVSZ];   // [16384, 768] (q|k|v)
__device__ float g_kt  [XSZ];     // [B, 256, 1024]
__device__ float g_o   [XSZ];
__device__ float g_t   [XSZ];
__device__ float g_h2  [XSZ];
__device__ float g_h1  [H1SZ];
__device__ float g_s   [SSZ];
__device__ float g_rmax[NROWS];
__device__ float g_rinv[NROWS];
__device__ float g_wqkv[Hd * 3 * Hd];

// ---------------------------------------------------------------------------
__device__ __forceinline__ unsigned f2tf(float f)
{
    unsigned u;
    asm("cvt.rna.tf32.f32 %0, %1;" : "=r"(u) : "f"(f));
    return u;
}

#define TF32_MMA(d, a, b)                                                     \
    asm volatile(                                                             \
        "mma.sync.aligned.m16n8k8.row.col.f32.tf32.tf32.f32 "                 \
        "{%0,%1,%2,%3},{%4,%5,%6,%7},{%8,%9},{%0,%1,%2,%3};"                  \
        : "+f"((d)[0]), "+f"((d)[1]), "+f"((d)[2]), "+f"((d)[3])              \
        : "r"((a)[0]), "r"((a)[1]), "r"((a)[2]), "r"((a)[3]),                 \
          "r"((b)[0]), "r"((b)[1]))

// ---------------------------------------------------------------------------
__global__ void embed_kernel(const int* __restrict__ ents,
                             const int* __restrict__ rels,
                             const float* __restrict__ ent_table,
                             const float* __restrict__ rel_table,
                             float* __restrict__ x)
{
    int bn = blockIdx.x;
    int b  = bn >> 10;
    int n  = bn & 1023;
    const float* src;
    if (n < Ee)            src = ent_table + (size_t)ents[b * Ee + n] * Hd;
    else if (n < Ee + Rr)  src = rel_table + (size_t)rels[b * Rr + (n - Ee)] * Hd;
    else                   src = rel_table + (size_t)ROOTI * Hd;
    x[(size_t)bn * Hd + threadIdx.x] = src[threadIdx.x];
}

// ---------------------------------------------------------------------------
__global__ void packw_kernel(const float* __restrict__ wq,
                             const float* __restrict__ wk,
                             const float* __restrict__ wv,
                             float* __restrict__ out)
{
    int i = blockIdx.x * blockDim.x + threadIdx.x;
    int k = i / 768, c = i - k * 768;
    float v;
    if (c < 256)      v = wq[k * 256 + c];
    else if (c < 512) v = wk[k * 256 + c - 256];
    else              v = wv[k * 256 + c - 512];
    out[i] = v;
}

// ---------------------------------------------------------------------------
// tf32 tensor-core GEMM: C[M,Nc] = A @ W.  Block 128x128, kstep 16,
// 8 warps (2x4), warp tile 64x32 (m16n8k8). mode: 0 plain, 1 bias+PReLU, 2 bias.
// ---------------------------------------------------------------------------
__global__ void __launch_bounds__(256, 2)
gemm_tc(const float* __restrict__ A,
        const float* __restrict__ W,
        float* __restrict__ C,
        int K, int lda, int ldb, int ldc,
        const float* __restrict__ bias,
        const float* __restrict__ alpha,
        int mode)
{
    __shared__ unsigned As[2][16][132];
    __shared__ unsigned Bs[2][16][132];

    int t    = threadIdx.x;
    int w    = t >> 5, lane = t & 31;
    int gid  = lane >> 2, tid4 = lane & 3;
    int wm0  = (w >> 2) * 64;
    int wn0  = (w & 3) * 32;
    int row0 = blockIdx.y << 7;
    int col0 = blockIdx.x << 7;

    int am = t >> 1;
    int ak = (t & 1) * 8;
    int bk = t >> 4;
    int bc = (t & 15) * 4;

    const float* Ap = A + (size_t)(row0 + am) * lda + ak;
    const float* Bp = W + (size_t)bk * ldb + col0 + bc;

    {
        float4 a0 = *(const float4*)Ap;
        float4 a1 = *(const float4*)(Ap + 4);
        float4 b0 = *(const float4*)Bp;
        float4 b1 = *(const float4*)(Bp + 64);
        As[0][ak + 0][am] = f2tf(a0.x); As[0][ak + 1][am] = f2tf(a0.y);
        As[0][ak + 2][am] = f2tf(a0.z); As[0][ak + 3][am] = f2tf(a0.w);
        As[0][ak + 4][am] = f2tf(a1.x); As[0][ak + 5][am] = f2tf(a1.y);
        As[0][ak + 6][am] = f2tf(a1.z); As[0][ak + 7][am] = f2tf(a1.w);
        Bs[0][bk][bc + 0] = f2tf(b0.x); Bs[0][bk][bc + 1] = f2tf(b0.y);
        Bs[0][bk][bc + 2] = f2tf(b0.z); Bs[0][bk][bc + 3] = f2tf(b0.w);
        Bs[0][bk][bc + 64] = f2tf(b1.x); Bs[0][bk][bc + 65] = f2tf(b1.y);
        Bs[0][bk][bc + 66] = f2tf(b1.z); Bs[0][bk][bc + 67] = f2tf(b1.w);
    }
    __syncthreads();

    float acc[4][4][4] = {};
    int buf = 0;

    for (int k0 = 16; k0 <= K; k0 += 16) {
        float4 na0, na1, nb0, nb1;
        if (k0 < K) {
            na0 = *(const float4*)(Ap + k0);
            na1 = *(const float4*)(Ap + k0 + 4);
            nb0 = *(const float4*)(Bp + (size_t)k0 * ldb);
            nb1 = *(const float4*)(Bp + (size_t)k0 * ldb + 64);
        }
#pragma unroll
        for (int ks = 0; ks < 16; ks += 8) {
            unsigned af[4][4], bf[4][2];
#pragma unroll
            for (int nt = 0; nt < 4; nt++) {
                bf[nt][0] = Bs[buf][ks + tid4][wn0 + nt * 8 + gid];
                bf[nt][1] = Bs[buf][ks + tid4 + 4][wn0 + nt * 8 + gid];
            }
#pragma unroll
            for (int mt = 0; mt < 4; mt++) {
                af[mt][0] = As[buf][ks + tid4][wm0 + mt * 16 + gid];
                af[mt][1] = As[buf][ks + tid4][wm0 + mt * 16 + gid + 8];
                af[mt][2] = As[buf][ks + tid4 + 4][wm0 + mt * 16 + gid];
                af[mt][3] = As[buf][ks + tid4 + 4][wm0 + mt * 16 + gid + 8];
            }
#pragma unroll
            for (int mt = 0; mt < 4; mt++)
#pragma unroll
                for (int nt = 0; nt < 4; nt++)
                    TF32_MMA(acc[mt][nt], af[mt], bf[nt]);
        }
        if (k0 < K) {
            buf ^= 1;
            As[buf][ak + 0][am] = f2tf(na0.x); As[buf][ak + 1][am] = f2tf(na0.y);
            As[buf][ak + 2][am] = f2tf(na0.z); As[buf][ak + 3][am] = f2tf(na0.w);
            As[buf][ak + 4][am] = f2tf(na1.x); As[buf][ak + 5][am] = f2tf(na1.y);
            As[buf][ak + 6][am] = f2tf(na1.z); As[buf][ak + 7][am] = f2tf(na1.w);
            Bs[buf][bk][bc + 0] = f2tf(nb0.x); Bs[buf][bk][bc + 1] = f2tf(nb0.y);
            Bs[buf][bk][bc + 2] = f2tf(nb0.z); Bs[buf][bk][bc + 3] = f2tf(nb0.w);
            Bs[buf][bk][bc + 64] = f2tf(nb1.x); Bs[buf][bk][bc + 65] = f2tf(nb1.y);
            Bs[buf][bk][bc + 66] = f2tf(nb1.z); Bs[buf][bk][bc + 67] = f2tf(nb1.w);
            __syncthreads();
        }
    }

#pragma unroll
    for (int mt = 0; mt < 4; mt++) {
        int r0 = row0 + wm0 + mt * 16 + gid;
#pragma unroll
        for (int nt = 0; nt < 4; nt++) {
            int c = col0 + wn0 + nt * 8 + 2 * tid4;
            float v0 = acc[mt][nt][0], v1 = acc[mt][nt][1];
            float v2 = acc[mt][nt][2], v3 = acc[mt][nt][3];
            if (mode != 0) {
                float b0v = bias[c], b1v = bias[c + 1];
                v0 += b0v; v1 += b1v; v2 += b0v; v3 += b1v;
            }
            if (mode == 1) {
                float a0v = alpha[c], a1v = alpha[c + 1];
                v0 = v0 >= 0.f ? v0 : a0v * v0;
                v1 = v1 >= 0.f ? v1 : a1v * v1;
                v2 = v2 >= 0.f ? v2 : a0v * v2;
                v3 = v3 >= 0.f ? v3 : a1v * v3;
            }
            *(float2*)&C[(size_t)r0 * ldc + c]       = make_float2(v0, v1);
            *(float2*)&C[(size_t)(r0 + 8) * ldc + c] = make_float2(v2, v3);
        }
    }
}

// ---------------------------------------------------------------------------
// K transpose from packed qkv
// ---------------------------------------------------------------------------
__global__ void ktrans_kernel(const float* __restrict__ qkv, float* __restrict__ Kt)
{
    __shared__ float tile[32][33];
    int b  = blockIdx.z;
    int j0 = blockIdx.y << 5;
    int c0 = blockIdx.x << 5;
    int tx = threadIdx.x;
    int ty = threadIdx.y;
    const float* src = qkv + (size_t)b * Nn * 768 + 256;
#pragma unroll
    for (int r = ty; r < 32; r += 8)
        tile[r][tx] = src[(size_t)(j0 + r) * 768 + c0 + tx];
    __syncthreads();
    float* dst = Kt + (size_t)b * Hd * Nn;
#pragma unroll
    for (int r = ty; r < 32; r += 8)
        dst[(size_t)(c0 + r) * Nn + j0 + tx] = tile[tx][r];
}

// ---------------------------------------------------------------------------
// Score: per (b,h) 128x128 tile, K=64, tf32 mma. Epilogue mask+scale.
// grid (8, 8, 64)
// ---------------------------------------------------------------------------
__global__ void __launch_bounds__(256, 2)
score_tc(const float* __restrict__ qkv,
         const float* __restrict__ Kt,
         const int* __restrict__ adj,
         float* __restrict__ S)
{
    __shared__ unsigned As[2][16][132];
    __shared__ unsigned Bs[2][16][132];

    int t    = threadIdx.x;
    int w    = t >> 5, lane = t & 31;
    int gid  = lane >> 2, tid4 = lane & 3;
    int wm0  = (w >> 2) * 64;
    int wn0  = (w & 3) * 32;
    int z = blockIdx.z;
    int b = z >> 2, h = z & 3;
    int i0 = blockIdx.y << 7;
    int j0 = blockIdx.x << 7;

    int am = t >> 1;
    int ak = (t & 1) * 8;
    int bk = t >> 4;
    int bc = (t & 15) * 4;

    const float* Ap = qkv + (size_t)(b * Nn + i0 + am) * 768 + h * 64 + ak;
    const float* Bp = Kt + ((size_t)b * Hd + h * 64 + bk) * Nn + j0 + bc;

    {
        float4 a0 = *(const float4*)Ap;
        float4 a1 = *(const float4*)(Ap + 4);
        float4 b0 = *(const float4*)Bp;
        float4 b1 = *(const float4*)(Bp + 64);
        As[0][ak + 0][am] = f2tf(a0.x); As[0][ak + 1][am] = f2tf(a0.y);
        As[0][ak + 2][am] = f2tf(a0.z); As[0][ak + 3][am] = f2tf(a0.w);
        As[0][ak + 4][am] = f2tf(a1.x); As[0][ak + 5][am] = f2tf(a1.y);
        As[0][ak + 6][am] = f2tf(a1.z); As[0][ak + 7][am] = f2tf(a1.w);
        Bs[0][bk][bc + 0] = f2tf(b0.x); Bs[0][bk][bc + 1] = f2tf(b0.y);
        Bs[0][bk][bc + 2] = f2tf(b0.z); Bs[0][bk][bc + 3] = f2tf(b0.w);
        Bs[0][bk][bc + 64] = f2tf(b1.x); Bs[0][bk][bc + 65] = f2tf(b1.y);
        Bs[0][bk][bc + 66] = f2tf(b1.z); Bs[0][bk][bc + 67] = f2tf(b1.w);
    }
    __syncthreads();

    float acc[4][4][4] = {};
    int buf = 0;

    for (int k0 = 16; k0 <= 64; k0 += 16) {
        float4 na0, na1, nb0, nb1;
        if (k0 < 64) {
            na0 = *(const float4*)(Ap + k0);
            na1 = *(const float4*)(Ap + k0 + 4);
            nb0 = *(const float4*)(Bp + (size_t)k0 * Nn);
            nb1 = *(const float4*)(Bp + (size_t)k0 * Nn + 64);
        }
#pragma unroll
        for (int ks = 0; ks < 16; ks += 8) {
            unsigned af[4][4], bf[4][2];
#pragma unroll
            for (int nt = 0; nt < 4; nt++) {
                bf[nt][0] = Bs[buf][ks + tid4][wn0 + nt * 8 + gid];
                bf[nt][1] = Bs[buf][ks + tid4 + 4][wn0 + nt * 8 + gid];
            }
#pragma unroll
            for (int mt = 0; mt < 4; mt++) {
                af[mt][0] = As[buf][ks + tid4][wm0 + mt * 16 + gid];
                af[mt][1] = As[buf][ks + tid4][wm0 + mt * 16 + gid + 8];
                af[mt][2] = As[buf][ks + tid4 + 4][wm0 + mt * 16 + gid];
                af[mt][3] = As[buf][ks + tid4 + 4][wm0 + mt * 16 + gid + 8];
            }
#pragma unroll
            for (int mt = 0; mt < 4; mt++)
#pragma unroll
                for (int nt = 0; nt < 4; nt++)
                    TF32_MMA(acc[mt][nt], af[mt], bf[nt]);
        }
        if (k0 < 64) {
            buf ^= 1;
            As[buf][ak + 0][am] = f2tf(na0.x); As[buf][ak + 1][am] = f2tf(na0.y);
            As[buf][ak + 2][am] = f2tf(na0.z); As[buf][ak + 3][am] = f2tf(na0.w);
            As[buf][ak + 4][am] = f2tf(na1.x); As[buf][ak + 5][am] = f2tf(na1.y);
            As[buf][ak + 6][am] = f2tf(na1.z); As[buf][ak + 7][am] = f2tf(na1.w);
            Bs[buf][bk][bc + 0] = f2tf(nb0.x); Bs[buf][bk][bc + 1] = f2tf(nb0.y);
            Bs[buf][bk][bc + 2] = f2tf(nb0.z); Bs[buf][bk][bc + 3] = f2tf(nb0.w);
            Bs[buf][bk][bc + 64] = f2tf(nb1.x); Bs[buf][bk][bc + 65] = f2tf(nb1.y);
            Bs[buf][bk][bc + 66] = f2tf(nb1.z); Bs[buf][bk][bc + 67] = f2tf(nb1.w);
            __syncthreads();
        }
    }

    float* Sz = S + ((size_t)z << 20);
#pragma unroll
    for (int mt = 0; mt < 4; mt++) {
        int r0 = i0 + wm0 + mt * 16 + gid;
#pragma unroll
        for (int nt = 0; nt < 4; nt++) {
            int c = j0 + wn0 + nt * 8 + 2 * tid4;
            const int* arow0 = adj + ((size_t)(b * Nn + r0) << 10);
            const int* arow1 = adj + ((size_t)(b * Nn + r0 + 8) << 10);
            int2 m0 = *(const int2*)&arow0[c];
            int2 m1 = *(const int2*)&arow1[c];
            float2 o0, o1;
            o0.x = m0.x ? acc[mt][nt][0] * 0.0625f : -1e30f;
            o0.y = m0.y ? acc[mt][nt][1] * 0.0625f : -1e30f;
            o1.x = m1.x ? acc[mt][nt][2] * 0.0625f : -1e30f;
            o1.y = m1.y ? acc[mt][nt][3] * 0.0625f : -1e30f;
            *(float2*)&Sz[((size_t)r0 << 10) + c]       = o0;
            *(float2*)&Sz[((size_t)(r0 + 8) << 10) + c] = o1;
        }
    }
}

// ---------------------------------------------------------------------------
__global__ void rowstat_kernel(const float* __restrict__ S,
                               float* __restrict__ rmax,
                               float* __restrict__ rinv)
{
    __shared__ float red[256];
    int t = threadIdx.x;
    const float4* p = (const float4*)(S + ((size_t)blockIdx.x << 10));
    float4 v = p[t];

    float mx = fmaxf(fmaxf(v.x, v.y), fmaxf(v.z, v.w));
    red[t] = mx;
    __syncthreads();
#pragma unroll
    for (int off = 128; off > 0; off >>= 1) {
        if (t < off) red[t] = fmaxf(red[t], red[t + off]);
        __syncthreads();
    }
    mx = red[0];
    __syncthreads();

    float s = __expf(v.x - mx) + __expf(v.y - mx)
            + __expf(v.z - mx) + __expf(v.w - mx);
    red[t] = s;
    __syncthreads();
#pragma unroll
    for (int off = 128; off > 0; off >>= 1) {
        if (t < off) red[t] += red[t + off];
        __syncthreads();
    }
    if (t == 0) {
        rmax[blockIdx.x] = mx;
        rinv[blockIdx.x] = 1.f / red[0];
    }
}

// ---------------------------------------------------------------------------
// AV: per (b,h) 128x64 tile, K=1024, tf32 mma. A = exp(S-max)*inv on the fly.
// 8 warps (4x2), warp tile 32x32. grid (8, 64).
// ---------------------------------------------------------------------------
__global__ void __launch_bounds__(256, 2)
av_tc(const float* __restrict__ S,
      const float* __restrict__ qkv,
      const float* __restrict__ rmax,
      const float* __restrict__ rinv,
      const float* __restrict__ X,
      float* __restrict__ O)
{
    __shared__ unsigned As[2][16][132];
    __shared__ unsigned Bs[2][16][68];

    int t    = threadIdx.x;
    int w    = t >> 5, lane = t & 31;
    int gid  = lane >> 2, tid4 = lane & 3;
    int wm0  = (w >> 1) * 32;
    int wn0  = (w & 1) * 32;
    int z = blockIdx.y;
    int b = z >> 2, h = z & 3;
    int i0 = blockIdx.x << 7;

    int am = t >> 1;
    int ak = (t & 1) * 8;
    int bk = t >> 4;
    int bc = (t & 15) * 4;

    const float* Ap = S + ((size_t)z << 20) + ((size_t)(i0 + am) << 10) + ak;
    const float* Bp = qkv + (size_t)bk * 768 + (size_t)b * Nn * 768 + 512 + h * 64 + bc;

    float rm = rmax[(z << 10) + i0 + am];
    float ri = rinv[(z << 10) + i0 + am];

    {
        float4 a0 = *(const float4*)Ap;
        float4 a1 = *(const float4*)(Ap + 4);
        float4 b0 = *(const float4*)Bp;
        As[0][ak + 0][am] = f2tf(__expf(a0.x - rm) * ri);
        As[0][ak + 1][am] = f2tf(__expf(a0.y - rm) * ri);
        As[0][ak + 2][am] = f2tf(__expf(a0.z - rm) * ri);
        As[0][ak + 3][am] = f2tf(__expf(a0.w - rm) * ri);
        As[0][ak + 4][am] = f2tf(__expf(a1.x - rm) * ri);
        As[0][ak + 5][am] = f2tf(__expf(a1.y - rm) * ri);
        As[0][ak + 6][am] = f2tf(__expf(a1.z - rm) * ri);
        As[0][ak + 7][am] = f2tf(__expf(a1.w - rm) * ri);
        Bs[0][bk][bc + 0] = f2tf(b0.x); Bs[0][bk][bc + 1] = f2tf(b0.y);
        Bs[0][bk][bc + 2] = f2tf(b0.z); Bs[0][bk][bc + 3] = f2tf(b0.w);
    }
    __syncthreads();

    float acc[2][4][4] = {};
    int buf = 0;

    for (int k0 = 16; k0 <= Nn; k0 += 16) {
        float4 na0, na1, nb0;
        if (k0 < Nn) {
            na0 = *(const float4*)(Ap + k0);
            na1 = *(const float4*)(Ap + k0 + 4);
            nb0 = *(const float4*)(Bp + (size_t)k0 * 768);
        }
#pragma unroll
        for (int ks = 0; ks < 16; ks += 8) {
            unsigned af[2][4], bf[4][2];
#pragma unroll
            for (int nt = 0; nt < 4; nt++) {
                bf[nt][0] = Bs[buf][ks + tid4][wn0 + nt * 8 + gid];
                bf[nt][1] = Bs[buf][ks + tid4 + 4][wn0 + nt * 8 + gid];
            }
#pragma unroll
            for (int mt = 0; mt < 2; mt++) {
                af[mt][0] = As[buf][ks + tid4][wm0 + mt * 16 + gid];
                af[mt][1] = As[buf][ks + tid4][wm0 + mt * 16 + gid + 8];
                af[mt][2] = As[buf][ks + tid4 + 4][wm0 + mt * 16 + gid];
                af[mt][3] = As[buf][ks + tid4 + 4][wm0 + mt * 16 + gid + 8];
            }
#pragma unroll
            for (int mt = 0; mt < 2; mt++)
#pragma unroll
                for (int nt = 0; nt < 4; nt++)
                    TF32_MMA(acc[mt][nt], af[mt], bf[nt]);
        }
        if (k0 < Nn) {
            buf ^= 1;
            As[buf][ak + 0][am] = f2tf(__expf(na0.x - rm) * ri);
            As[buf][ak + 1][am] = f2tf(__expf(na0.y - rm) * ri);
            As[buf][ak + 2][am] = f2tf(__expf(na0.z - rm) * ri);
            As[buf][ak + 3][am] = f2tf(__expf(na0.w - rm) * ri);
            As[buf][ak + 4][am] = f2tf(__expf(na1.x - rm) * ri);
            As[buf][ak + 5][am] = f2tf(__expf(na1.y - rm) * ri);
            As[buf][ak + 6][am] = f2tf(__expf(na1.z - rm) * ri);
            As[buf][ak + 7][am] = f2tf(__expf(na1.w - rm) * ri);
            Bs[buf][bk][bc + 0] = f2tf(nb0.x); Bs[buf][bk][bc + 1] = f2tf(nb0.y);
            Bs[buf][bk][bc + 2] = f2tf(nb0.z); Bs[buf][bk][bc + 3] = f2tf(nb0.w);
            __syncthreads();
        }
    }

#pragma unroll
    for (int mt = 0; mt < 2; mt++) {
        int r0 = i0 + wm0 + mt * 16 + gid;
#pragma unroll
        for (int nt = 0; nt < 4; nt++) {
            int c = wn0 + nt * 8 + 2 * tid4;
            size_t idx0 = (size_t)(b * Nn + r0) * Hd + h * 64 + c;
            size_t idx1 = (size_t)(b * Nn + r0 + 8) * Hd + h * 64 + c;
            float2 x0 = *(const float2*)&X[idx0];
            float2 x1 = *(const float2*)&X[idx1];
            float2 o0 = make_float2(acc[mt][nt][0] + x0.x, acc[mt][nt][1] + x0.y);
            float2 o1 = make_float2(acc[mt][nt][2] + x1.x, acc[mt][nt][3] + x1.y);
            *(float2*)&O[idx0] = o0;
            *(float2*)&O[idx1] = o1;
        }
    }
}

// ---------------------------------------------------------------------------
__global__ void ln_kernel(const float* __restrict__ A,
                          const float* __restrict__ Badd,
                          const float* __restrict__ gamma,
                          const float* __restrict__ beta,
                          float* __restrict__ out)
{
    __shared__ float red[256];
    int row = blockIdx.x;
    int t   = threadIdx.x;
    size_t idx = (size_t)row * Hd + t;
    float v = A[idx];
    if (Badd) v += Badd[idx];

    red[t] = v;
    __syncthreads();
#pragma unroll
    for (int off = 128; off > 0; off >>= 1) {
        if (t < off) red[t] += red[t + off];
        __syncthreads();
    }
    float mean = red[0] * (1.f / Hd);
    __syncthreads();

    float d = v - mean;
    red[t] = d * d;
    __syncthreads();
#pragma unroll
    for (int off = 128; off > 0; off >>= 1) {
        if (t < off) red[t] += red[t + off];
        __syncthreads();
    }
    float var = red[0] * (1.f / Hd);
    out[idx] = d * rsqrtf(var + 1e-5f) * gamma[t] + beta[t];
}

// ---------------------------------------------------------------------------
__global__ void fill_tail_kernel(float* __restrict__ out, int start, int total)
{
    int i = blockIdx.x * blockDim.x + threadIdx.x + start;
    if (i < total) out[i] = 1.0f;
}

// ---------------------------------------------------------------------------
extern "C" void kernel_launch(void* const* d_in, const int* in_sizes, int n_in,
                              void* d_out, int out_size)
{
    const int*   ents      = (const int*)  d_in[0];
    const int*   rels      = (const int*)  d_in[1];
    const int*   adjs      = (const int*)  d_in[2];
    const float* ent_table = (const float*)d_in[3];
    const float* rel_table = (const float*)d_in[4];
    const float* Wq        = (const float*)d_in[5];
    const float* Wk        = (const float*)d_in[6];
    const float* Wv        = (const float*)d_in[7];
    const float* l1w       = (const float*)d_in[8];
    const float* l1b       = (const float*)d_in[9];
    const float* l2w       = (const float*)d_in[10];
    const float* l2b       = (const float*)d_in[11];
    const float* ln_g      = (const float*)d_in[12];
    const float* ln_b      = (const float*)d_in[13];
    const float* alpha     = (const float*)d_in[14];
    float* out = (float*)d_out;

    float *x, *qkv, *kt, *o, *tb, *h1, *h2, *s, *rmax, *rinv, *wqkv;
    cudaGetSymbolAddress((void**)&x,    g_x);
    cudaGetSymbolAddress((void**)&qkv,  g_qkv);
    cudaGetSymbolAddress((void**)&kt,   g_kt);
    cudaGetSymbolAddress((void**)&o,    g_o);
    cudaGetSymbolAddress((void**)&tb,   g_t);
    cudaGetSymbolAddress((void**)&h1,   g_h1);
    cudaGetSymbolAddress((void**)&h2,   g_h2);
    cudaGetSymbolAddress((void**)&s,    g_s);
    cudaGetSymbolAddress((void**)&rmax, g_rmax);
    cudaGetSymbolAddress((void**)&rinv, g_rinv);
    cudaGetSymbolAddress((void**)&wqkv, g_wqkv);

    embed_kernel<<<Bsz * Nn, 256>>>(ents, rels, ent_table, rel_table, x);

    for (int j = 0; j < 2; j++) {
        const float* wq = Wq  + (size_t)j * Hd * Hd;
        const float* wk = Wk  + (size_t)j * Hd * Hd;
        const float* wv = Wv  + (size_t)j * Hd * Hd;
        const float* w1 = l1w + (size_t)j * Hd * 4 * Hd;
        const float* b1 = l1b + (size_t)j * 4 * Hd;
        const float* w2 = l2w + (size_t)j * 4 * Hd * Hd;
        const float* b2 = l2b + (size_t)j * Hd;
        const float* lg = ln_g + (size_t)j * Hd;
        const float* lb = ln_b + (size_t)j * Hd;
        const float* al = alpha + (size_t)j * 4 * Hd;

        packw_kernel<<<768, 256>>>(wq, wk, wv, wqkv);

        // fused QKV: [16384,256] @ [256,768]
        gemm_tc<<<dim3(6, 128), 256>>>(x, wqkv, qkv,
                                       Hd, Hd, 768, 768, nullptr, nullptr, 0);

        ktrans_kernel<<<dim3(8, 32, Bsz), dim3(32, 8)>>>(qkv, kt);

        score_tc<<<dim3(8, 8, Bsz * 4), 256>>>(qkv, kt, adjs, s);
        rowstat_kernel<<<NROWS, 256>>>(s, rmax, rinv);
        av_tc<<<dim3(8, Bsz * 4), 256>>>(s, qkv, rmax, rinv, x, o);

        ln_kernel<<<Mrows, 256>>>(o, nullptr, lg, lb, tb);

        // MLP1: [16384,256] @ [256,1024]
        gemm_tc<<<dim3(8, 128), 256>>>(tb, w1, h1,
                                       Hd, Hd, 4 * Hd, 4 * Hd, b1, al, 1);
        // MLP2: [16384,1024] @ [1024,256]
        gemm_tc<<<dim3(2, 128), 256>>>(h1, w2, h2,
                                       4 * Hd, 4 * Hd, Hd, Hd, b2, nullptr, 2);

        float* dst = (j == 1) ? out : x;
        ln_kernel<<<Mrows, 256>>>(h2, tb, lg, lb, dst);
    }

    int tail = out_size - XSZ;
    if (tail > 0)
        fill_tail_kernel<<<(tail + 255) / 256, 256>>>(out, XSZ, out_size);
}

// round 6
// speedup vs baseline: 11.9734x; 1.1796x over previous
#include <cuda_runtime.h>
#include <cuda_bf16.h>

// ---------------------------------------------------------------------------
// graph_encoder: B=16, N=1024, H=256, 4 heads (d=64), 2 layers.
// R5: fused flash-attention (no S materialization) + tf32 mma GEMMs.
// ---------------------------------------------------------------------------

#define Bsz   16
#define Nn    1024
#define Hd    256
#define Ee    767
#define Rr    256
#define ROOTI 46
#define Mrows (Bsz * Nn)
#define XSZ   (Mrows * Hd)
#define H1SZ  (Mrows * 4 * Hd)
#define QKVSZ (Mrows * 3 * Hd)

__device__ float g_x   [XSZ];
__device__ float g_qkv [QKVSZ];   // [16384, 768] (q|k|v)
__device__ float g_kt  [XSZ];     // [B, 256, 1024]
__device__ float g_o   [XSZ];
__device__ float g_t   [XSZ];
__device__ float g_h2  [XSZ];
__device__ float g_h1  [H1SZ];
__device__ float g_wqkv[Hd * 3 * Hd];

// ---------------------------------------------------------------------------
__device__ __forceinline__ unsigned f2tf(float f)
{
    unsigned u;
    asm("cvt.rna.tf32.f32 %0, %1;" : "=r"(u) : "f"(f));
    return u;
}

#define TF32_MMA(d, a, b)                                                     \
    asm volatile(                                                             \
        "mma.sync.aligned.m16n8k8.row.col.f32.tf32.tf32.f32 "                 \
        "{%0,%1,%2,%3},{%4,%5,%6,%7},{%8,%9},{%0,%1,%2,%3};"                  \
        : "+f"((d)[0]), "+f"((d)[1]), "+f"((d)[2]), "+f"((d)[3])              \
        : "r"((a)[0]), "r"((a)[1]), "r"((a)[2]), "r"((a)[3]),                 \
          "r"((b)[0]), "r"((b)[1]))

// ---------------------------------------------------------------------------
__global__ void embed_kernel(const int* __restrict__ ents,
                             const int* __restrict__ rels,
                             const float* __restrict__ ent_table,
                             const float* __restrict__ rel_table,
                             float* __restrict__ x)
{
    int bn = blockIdx.x;
    int b  = bn >> 10;
    int n  = bn & 1023;
    const float* src;
    if (n < Ee)            src = ent_table + (size_t)ents[b * Ee + n] * Hd;
    else if (n < Ee + Rr)  src = rel_table + (size_t)rels[b * Rr + (n - Ee)] * Hd;
    else                   src = rel_table + (size_t)ROOTI * Hd;
    x[(size_t)bn * Hd + threadIdx.x] = src[threadIdx.x];
}

// ---------------------------------------------------------------------------
__global__ void packw_kernel(const float* __restrict__ wq,
                             const float* __restrict__ wk,
                             const float* __restrict__ wv,
                             float* __restrict__ out)
{
    int i = blockIdx.x * blockDim.x + threadIdx.x;
    int k = i / 768, c = i - k * 768;
    float v;
    if (c < 256)      v = wq[k * 256 + c];
    else if (c < 512) v = wk[k * 256 + c - 256];
    else              v = wv[k * 256 + c - 512];
    out[i] = v;
}

// ---------------------------------------------------------------------------
// tf32 tensor-core GEMM: 128x128 block, 8 warps (2x4), warp tile 64x32.
// mode: 0 plain, 1 bias+PReLU, 2 bias.
// ---------------------------------------------------------------------------
__global__ void __launch_bounds__(256, 2)
gemm_tc(const float* __restrict__ A,
        const float* __restrict__ W,
        float* __restrict__ C,
        int K, int lda, int ldb, int ldc,
        const float* __restrict__ bias,
        const float* __restrict__ alpha,
        int mode)
{
    __shared__ unsigned As[2][16][132];
    __shared__ unsigned Bs[2][16][132];

    int t    = threadIdx.x;
    int w    = t >> 5, lane = t & 31;
    int gid  = lane >> 2, tid4 = lane & 3;
    int wm0  = (w >> 2) * 64;
    int wn0  = (w & 3) * 32;
    int row0 = blockIdx.y << 7;
    int col0 = blockIdx.x << 7;

    int am = t >> 1;
    int ak = (t & 1) * 8;
    int bk = t >> 4;
    int bc = (t & 15) * 4;

    const float* Ap = A + (size_t)(row0 + am) * lda + ak;
    const float* Bp = W + (size_t)bk * ldb + col0 + bc;

    {
        float4 a0 = *(const float4*)Ap;
        float4 a1 = *(const float4*)(Ap + 4);
        float4 b0 = *(const float4*)Bp;
        float4 b1 = *(const float4*)(Bp + 64);
        As[0][ak + 0][am] = f2tf(a0.x); As[0][ak + 1][am] = f2tf(a0.y);
        As[0][ak + 2][am] = f2tf(a0.z); As[0][ak + 3][am] = f2tf(a0.w);
        As[0][ak + 4][am] = f2tf(a1.x); As[0][ak + 5][am] = f2tf(a1.y);
        As[0][ak + 6][am] = f2tf(a1.z); As[0][ak + 7][am] = f2tf(a1.w);
        Bs[0][bk][bc + 0] = f2tf(b0.x); Bs[0][bk][bc + 1] = f2tf(b0.y);
        Bs[0][bk][bc + 2] = f2tf(b0.z); Bs[0][bk][bc + 3] = f2tf(b0.w);
        Bs[0][bk][bc + 64] = f2tf(b1.x); Bs[0][bk][bc + 65] = f2tf(b1.y);
        Bs[0][bk][bc + 66] = f2tf(b1.z); Bs[0][bk][bc + 67] = f2tf(b1.w);
    }
    __syncthreads();

    float acc[4][4][4] = {};
    int buf = 0;

    for (int k0 = 16; k0 <= K; k0 += 16) {
        float4 na0, na1, nb0, nb1;
        if (k0 < K) {
            na0 = *(const float4*)(Ap + k0);
            na1 = *(const float4*)(Ap + k0 + 4);
            nb0 = *(const float4*)(Bp + (size_t)k0 * ldb);
            nb1 = *(const float4*)(Bp + (size_t)k0 * ldb + 64);
        }
#pragma unroll
        for (int ks = 0; ks < 16; ks += 8) {
            unsigned af[4][4], bf[4][2];
#pragma unroll
            for (int nt = 0; nt < 4; nt++) {
                bf[nt][0] = Bs[buf][ks + tid4][wn0 + nt * 8 + gid];
                bf[nt][1] = Bs[buf][ks + tid4 + 4][wn0 + nt * 8 + gid];
            }
#pragma unroll
            for (int mt = 0; mt < 4; mt++) {
                af[mt][0] = As[buf][ks + tid4][wm0 + mt * 16 + gid];
                af[mt][1] = As[buf][ks + tid4][wm0 + mt * 16 + gid + 8];
                af[mt][2] = As[buf][ks + tid4 + 4][wm0 + mt * 16 + gid];
                af[mt][3] = As[buf][ks + tid4 + 4][wm0 + mt * 16 + gid + 8];
            }
#pragma unroll
            for (int mt = 0; mt < 4; mt++)
#pragma unroll
                for (int nt = 0; nt < 4; nt++)
                    TF32_MMA(acc[mt][nt], af[mt], bf[nt]);
        }
        if (k0 < K) {
            buf ^= 1;
            As[buf][ak + 0][am] = f2tf(na0.x); As[buf][ak + 1][am] = f2tf(na0.y);
            As[buf][ak + 2][am] = f2tf(na0.z); As[buf][ak + 3][am] = f2tf(na0.w);
            As[buf][ak + 4][am] = f2tf(na1.x); As[buf][ak + 5][am] = f2tf(na1.y);
            As[buf][ak + 6][am] = f2tf(na1.z); As[buf][ak + 7][am] = f2tf(na1.w);
            Bs[buf][bk][bc + 0] = f2tf(nb0.x); Bs[buf][bk][bc + 1] = f2tf(nb0.y);
            Bs[buf][bk][bc + 2] = f2tf(nb0.z); Bs[buf][bk][bc + 3] = f2tf(nb0.w);
            Bs[buf][bk][bc + 64] = f2tf(nb1.x); Bs[buf][bk][bc + 65] = f2tf(nb1.y);
            Bs[buf][bk][bc + 66] = f2tf(nb1.z); Bs[buf][bk][bc + 67] = f2tf(nb1.w);
            __syncthreads();
        }
    }

#pragma unroll
    for (int mt = 0; mt < 4; mt++) {
        int r0 = row0 + wm0 + mt * 16 + gid;
#pragma unroll
        for (int nt = 0; nt < 4; nt++) {
            int c = col0 + wn0 + nt * 8 + 2 * tid4;
            float v0 = acc[mt][nt][0], v1 = acc[mt][nt][1];
            float v2 = acc[mt][nt][2], v3 = acc[mt][nt][3];
            if (mode != 0) {
                float b0v = bias[c], b1v = bias[c + 1];
                v0 += b0v; v1 += b1v; v2 += b0v; v3 += b1v;
            }
            if (mode == 1) {
                float a0v = alpha[c], a1v = alpha[c + 1];
                v0 = v0 >= 0.f ? v0 : a0v * v0;
                v1 = v1 >= 0.f ? v1 : a1v * v1;
                v2 = v2 >= 0.f ? v2 : a0v * v2;
                v3 = v3 >= 0.f ? v3 : a1v * v3;
            }
            *(float2*)&C[(size_t)r0 * ldc + c]       = make_float2(v0, v1);
            *(float2*)&C[(size_t)(r0 + 8) * ldc + c] = make_float2(v2, v3);
        }
    }
}

// ---------------------------------------------------------------------------
__global__ void ktrans_kernel(const float* __restrict__ qkv, float* __restrict__ Kt)
{
    __shared__ float tile[32][33];
    int b  = blockIdx.z;
    int j0 = blockIdx.y << 5;
    int c0 = blockIdx.x << 5;
    int tx = threadIdx.x;
    int ty = threadIdx.y;
    const float* src = qkv + (size_t)b * Nn * 768 + 256;
#pragma unroll
    for (int r = ty; r < 32; r += 8)
        tile[r][tx] = src[(size_t)(j0 + r) * 768 + c0 + tx];
    __syncthreads();
    float* dst = Kt + (size_t)b * Hd * Nn;
#pragma unroll
    for (int r = ty; r < 32; r += 8)
        dst[(size_t)(c0 + r) * Nn + j0 + tx] = tile[tx][r];
}

// ---------------------------------------------------------------------------
// Fused flash attention: per (b,h) and 128-row i-tile. No S materialization.
// grid (8, 64), 256 threads, dynamic smem.
// Smem layout (u32 words): Qs[64][136] Ks[64][136] Vs[128][72] Ps[128][136]
// plus float redm[4][128], reds[4][128].
// ---------------------------------------------------------------------------
#define FL_QS   0
#define FL_KS   (64 * 136)
#define FL_VS   (FL_KS + 64 * 136)
#define FL_PS   (FL_VS + 128 * 72)
#define FL_RED  (FL_PS + 128 * 136)
#define FL_SMEM ((FL_RED + 2 * 4 * 128) * 4)

__global__ void __launch_bounds__(256, 1)
flash_attn(const float* __restrict__ qkv,
           const float* __restrict__ Kt,
           const int* __restrict__ adj,
           const float* __restrict__ X,
           float* __restrict__ O)
{
    extern __shared__ unsigned sm[];
    unsigned* Qs = sm + FL_QS;
    unsigned* Ks = sm + FL_KS;
    unsigned* Vs = sm + FL_VS;
    unsigned* Ps = sm + FL_PS;
    float* redm = (float*)(sm + FL_RED);
    float* reds = redm + 4 * 128;

    int t = threadIdx.x;
    int w = t >> 5, lane = t & 31;
    int gid = lane >> 2, tid4 = lane & 3;
    int wm0 = (w >> 2) * 64;    // rows (i) this warp owns (both mmas)
    int wn0 = (w & 3) * 32;     // S cols (j)
    int wd0 = (w & 3) * 16;     // O cols (d)
    int z = blockIdx.y;
    int b = z >> 2, h = z & 3;
    int i0 = blockIdx.x << 7;

    // ---- Q tile: Qs[d][i] (tf32), once ----
    {
        int i  = t >> 1;
        int dh = (t & 1) * 32;
        const float* src = qkv + (size_t)(b * Nn + i0 + i) * 768 + h * 64 + dh;
#pragma unroll
        for (int c = 0; c < 32; c += 4) {
            float4 v = *(const float4*)(src + c);
            Qs[(dh + c + 0) * 136 + i] = f2tf(v.x);
            Qs[(dh + c + 1) * 136 + i] = f2tf(v.y);
            Qs[(dh + c + 2) * 136 + i] = f2tf(v.z);
            Qs[(dh + c + 3) * 136 + i] = f2tf(v.w);
        }
    }

    float m_st[8], l_st[8];
    float oac[4][2][4] = {};
#pragma unroll
    for (int s = 0; s < 8; s++) { m_st[s] = -1e4f; l_st[s] = 0.f; }

    for (int jt = 0; jt < 8; jt++) {
        int j0 = jt << 7;
        __syncthreads();   // protect Ks/Vs/Ps (and Qs on first iter)

        // ---- K tile: Ks[d][j] from Kt ----
        {
            int d  = t >> 2;
            int c0 = (t & 3) * 32;
            const float* src = Kt + ((size_t)b * Hd + h * 64 + d) * Nn + j0 + c0;
#pragma unroll
            for (int c = 0; c < 32; c += 4) {
                float4 v = *(const float4*)(src + c);
                uint4 u = make_uint4(f2tf(v.x), f2tf(v.y), f2tf(v.z), f2tf(v.w));
                *(uint4*)&Ks[d * 136 + c0 + c] = u;
            }
        }
        // ---- V tile: Vs[j][d] ----
        {
            int j  = t >> 1;
            int dh = (t & 1) * 32;
            const float* src = qkv + (size_t)(b * Nn + j0 + j) * 768 + 512 + h * 64 + dh;
#pragma unroll
            for (int c = 0; c < 32; c += 4) {
                float4 v = *(const float4*)(src + c);
                uint4 u = make_uint4(f2tf(v.x), f2tf(v.y), f2tf(v.z), f2tf(v.w));
                *(uint4*)&Vs[j * 72 + dh + c] = u;
            }
        }
        __syncthreads();

        // ---- S = Q @ K^T (128x128, k=64) ----
        float sac[4][4][4] = {};
#pragma unroll
        for (int ks = 0; ks < 64; ks += 8) {
            unsigned af[4][4], bf[4][2];
#pragma unroll
            for (int nt = 0; nt < 4; nt++) {
                bf[nt][0] = Ks[(ks + tid4) * 136 + wn0 + nt * 8 + gid];
                bf[nt][1] = Ks[(ks + tid4 + 4) * 136 + wn0 + nt * 8 + gid];
            }
#pragma unroll
            for (int mt = 0; mt < 4; mt++) {
                af[mt][0] = Qs[(ks + tid4) * 136 + wm0 + mt * 16 + gid];
                af[mt][1] = Qs[(ks + tid4) * 136 + wm0 + mt * 16 + gid + 8];
                af[mt][2] = Qs[(ks + tid4 + 4) * 136 + wm0 + mt * 16 + gid];
                af[mt][3] = Qs[(ks + tid4 + 4) * 136 + wm0 + mt * 16 + gid + 8];
            }
#pragma unroll
            for (int mt = 0; mt < 4; mt++)
#pragma unroll
                for (int nt = 0; nt < 4; nt++)
                    TF32_MMA(sac[mt][nt], af[mt], bf[nt]);
        }

        // ---- mask + scale, per-row tile max ----
        float tmax[8];
#pragma unroll
        for (int s = 0; s < 8; s++) tmax[s] = -1e30f;
#pragma unroll
        for (int mt = 0; mt < 4; mt++) {
            size_t r0 = (size_t)(b * Nn + i0 + wm0 + mt * 16 + gid);
            const int* a0 = adj + (r0 << 10) + j0;
            const int* a1 = adj + ((r0 + 8) << 10) + j0;
#pragma unroll
            for (int nt = 0; nt < 4; nt++) {
                int c = wn0 + nt * 8 + 2 * tid4;
                int2 m0v = *(const int2*)(a0 + c);
                int2 m1v = *(const int2*)(a1 + c);
                sac[mt][nt][0] = m0v.x ? sac[mt][nt][0] * 0.0625f : -1e30f;
                sac[mt][nt][1] = m0v.y ? sac[mt][nt][1] * 0.0625f : -1e30f;
                sac[mt][nt][2] = m1v.x ? sac[mt][nt][2] * 0.0625f : -1e30f;
                sac[mt][nt][3] = m1v.y ? sac[mt][nt][3] * 0.0625f : -1e30f;
                tmax[mt * 2 + 0] = fmaxf(tmax[mt * 2 + 0],
                                         fmaxf(sac[mt][nt][0], sac[mt][nt][1]));
                tmax[mt * 2 + 1] = fmaxf(tmax[mt * 2 + 1],
                                         fmaxf(sac[mt][nt][2], sac[mt][nt][3]));
            }
        }
#pragma unroll
        for (int s = 0; s < 8; s++) {
            tmax[s] = fmaxf(tmax[s], __shfl_xor_sync(0xffffffffu, tmax[s], 1));
            tmax[s] = fmaxf(tmax[s], __shfl_xor_sync(0xffffffffu, tmax[s], 2));
        }
        if (tid4 == 0) {
#pragma unroll
            for (int mt = 0; mt < 4; mt++) {
                redm[(w & 3) * 128 + wm0 + mt * 16 + gid]     = tmax[mt * 2];
                redm[(w & 3) * 128 + wm0 + mt * 16 + gid + 8] = tmax[mt * 2 + 1];
            }
        }
        __syncthreads();

        float alpha[8];
#pragma unroll
        for (int mt = 0; mt < 4; mt++)
#pragma unroll
            for (int q = 0; q < 2; q++) {
                int r = wm0 + mt * 16 + gid + q * 8;
                float tm = fmaxf(fmaxf(redm[r], redm[128 + r]),
                                 fmaxf(redm[256 + r], redm[384 + r]));
                int s = mt * 2 + q;
                float mn = fmaxf(m_st[s], fmaxf(tm, -1e4f));
                alpha[s] = __expf(m_st[s] - mn);
                m_st[s] = mn;
            }

        // ---- exp, partial sums, store P (tf32) ----
        float psum[8] = {};
#pragma unroll
        for (int mt = 0; mt < 4; mt++) {
            int r = wm0 + mt * 16 + gid;
            int s0 = mt * 2, s1 = mt * 2 + 1;
#pragma unroll
            for (int nt = 0; nt < 4; nt++) {
                int c = wn0 + nt * 8 + 2 * tid4;
                float e0 = __expf(sac[mt][nt][0] - m_st[s0]);
                float e1 = __expf(sac[mt][nt][1] - m_st[s0]);
                float e2 = __expf(sac[mt][nt][2] - m_st[s1]);
                float e3 = __expf(sac[mt][nt][3] - m_st[s1]);
                psum[s0] += e0 + e1;
                psum[s1] += e2 + e3;
                Ps[(c + 0) * 136 + r]     = f2tf(e0);
                Ps[(c + 1) * 136 + r]     = f2tf(e1);
                Ps[(c + 0) * 136 + r + 8] = f2tf(e2);
                Ps[(c + 1) * 136 + r + 8] = f2tf(e3);
            }
        }
#pragma unroll
        for (int s = 0; s < 8; s++) {
            psum[s] += __shfl_xor_sync(0xffffffffu, psum[s], 1);
            psum[s] += __shfl_xor_sync(0xffffffffu, psum[s], 2);
        }
        if (tid4 == 0) {
#pragma unroll
            for (int mt = 0; mt < 4; mt++) {
                reds[(w & 3) * 128 + wm0 + mt * 16 + gid]     = psum[mt * 2];
                reds[(w & 3) * 128 + wm0 + mt * 16 + gid + 8] = psum[mt * 2 + 1];
            }
        }
        __syncthreads();   // P complete + sums visible

        // ---- update l, rescale O ----
#pragma unroll
        for (int mt = 0; mt < 4; mt++)
#pragma unroll
            for (int q = 0; q < 2; q++) {
                int r = wm0 + mt * 16 + gid + q * 8;
                int s = mt * 2 + q;
                float ps = reds[r] + reds[128 + r] + reds[256 + r] + reds[384 + r];
                l_st[s] = l_st[s] * alpha[s] + ps;
            }
#pragma unroll
        for (int mt = 0; mt < 4; mt++)
#pragma unroll
            for (int nt = 0; nt < 2; nt++) {
                oac[mt][nt][0] *= alpha[mt * 2];
                oac[mt][nt][1] *= alpha[mt * 2];
                oac[mt][nt][2] *= alpha[mt * 2 + 1];
                oac[mt][nt][3] *= alpha[mt * 2 + 1];
            }

        // ---- O += P @ V (128x64, k=128) ----
#pragma unroll
        for (int ks = 0; ks < 128; ks += 8) {
            unsigned af[4][4], bf[2][2];
#pragma unroll
            for (int nt = 0; nt < 2; nt++) {
                bf[nt][0] = Vs[(ks + tid4) * 72 + wd0 + nt * 8 + gid];
                bf[nt][1] = Vs[(ks + tid4 + 4) * 72 + wd0 + nt * 8 + gid];
            }
#pragma unroll
            for (int mt = 0; mt < 4; mt++) {
                af[mt][0] = Ps[(ks + tid4) * 136 + wm0 + mt * 16 + gid];
                af[mt][1] = Ps[(ks + tid4) * 136 + wm0 + mt * 16 + gid + 8];
                af[mt][2] = Ps[(ks + tid4 + 4) * 136 + wm0 + mt * 16 + gid];
                af[mt][3] = Ps[(ks + tid4 + 4) * 136 + wm0 + mt * 16 + gid + 8];
            }
#pragma unroll
            for (int mt = 0; mt < 4; mt++)
#pragma unroll
                for (int nt = 0; nt < 2; nt++)
                    TF32_MMA(oac[mt][nt], af[mt], bf[nt]);
        }
    }

    // ---- epilogue: O/l + residual X ----
    float inv[8];
#pragma unroll
    for (int s = 0; s < 8; s++) inv[s] = 1.f / l_st[s];
#pragma unroll
    for (int mt = 0; mt < 4; mt++) {
        int r = i0 + wm0 + mt * 16 + gid;
#pragma unroll
        for (int nt = 0; nt < 2; nt++) {
            int c = wd0 + nt * 8 + 2 * tid4;
            size_t idx0 = (size_t)(b * Nn + r) * Hd + h * 64 + c;
            size_t idx1 = (size_t)(b * Nn + r + 8) * Hd + h * 64 + c;
            float2 x0 = *(const float2*)&X[idx0];
            float2 x1 = *(const float2*)&X[idx1];
            float2 o0 = make_float2(oac[mt][nt][0] * inv[mt * 2] + x0.x,
                                    oac[mt][nt][1] * inv[mt * 2] + x0.y);
            float2 o1 = make_float2(oac[mt][nt][2] * inv[mt * 2 + 1] + x1.x,
                                    oac[mt][nt][3] * inv[mt * 2 + 1] + x1.y);
            *(float2*)&O[idx0] = o0;
            *(float2*)&O[idx1] = o1;
        }
    }
}

// ---------------------------------------------------------------------------
__global__ void ln_kernel(const float* __restrict__ A,
                          const float* __restrict__ Badd,
                          const float* __restrict__ gamma,
                          const float* __restrict__ beta,
                          float* __restrict__ out)
{
    __shared__ float red[256];
    int row = blockIdx.x;
    int t   = threadIdx.x;
    size_t idx = (size_t)row * Hd + t;
    float v = A[idx];
    if (Badd) v += Badd[idx];

    red[t] = v;
    __syncthreads();
#pragma unroll
    for (int off = 128; off > 0; off >>= 1) {
        if (t < off) red[t] += red[t + off];
        __syncthreads();
    }
    float mean = red[0] * (1.f / Hd);
    __syncthreads();

    float d = v - mean;
    red[t] = d * d;
    __syncthreads();
#pragma unroll
    for (int off = 128; off > 0; off >>= 1) {
        if (t < off) red[t] += red[t + off];
        __syncthreads();
    }
    float var = red[0] * (1.f / Hd);
    out[idx] = d * rsqrtf(var + 1e-5f) * gamma[t] + beta[t];
}

// ---------------------------------------------------------------------------
__global__ void fill_tail_kernel(float* __restrict__ out, int start, int total)
{
    int i = blockIdx.x * blockDim.x + threadIdx.x + start;
    if (i < total) out[i] = 1.0f;
}

// ---------------------------------------------------------------------------
extern "C" void kernel_launch(void* const* d_in, const int* in_sizes, int n_in,
                              void* d_out, int out_size)
{
    const int*   ents      = (const int*)  d_in[0];
    const int*   rels      = (const int*)  d_in[1];
    const int*   adjs      = (const int*)  d_in[2];
    const float* ent_table = (const float*)d_in[3];
    const float* rel_table = (const float*)d_in[4];
    const float* Wq        = (const float*)d_in[5];
    const float* Wk        = (const float*)d_in[6];
    const float* Wv        = (const float*)d_in[7];
    const float* l1w       = (const float*)d_in[8];
    const float* l1b       = (const float*)d_in[9];
    const float* l2w       = (const float*)d_in[10];
    const float* l2b       = (const float*)d_in[11];
    const float* ln_g      = (const float*)d_in[12];
    const float* ln_b      = (const float*)d_in[13];
    const float* alpha     = (const float*)d_in[14];
    float* out = (float*)d_out;

    float *x, *qkv, *kt, *o, *tb, *h1, *h2, *wqkv;
    cudaGetSymbolAddress((void**)&x,    g_x);
    cudaGetSymbolAddress((void**)&qkv,  g_qkv);
    cudaGetSymbolAddress((void**)&kt,   g_kt);
    cudaGetSymbolAddress((void**)&o,    g_o);
    cudaGetSymbolAddress((void**)&tb,   g_t);
    cudaGetSymbolAddress((void**)&h1,   g_h1);
    cudaGetSymbolAddress((void**)&h2,   g_h2);
    cudaGetSymbolAddress((void**)&wqkv, g_wqkv);

    cudaFuncSetAttribute(flash_attn, cudaFuncAttributeMaxDynamicSharedMemorySize,
                         FL_SMEM);

    embed_kernel<<<Bsz * Nn, 256>>>(ents, rels, ent_table, rel_table, x);

    for (int j = 0; j < 2; j++) {
        const float* wq = Wq  + (size_t)j * Hd * Hd;
        const float* wk = Wk  + (size_t)j * Hd * Hd;
        const float* wv = Wv  + (size_t)j * Hd * Hd;
        const float* w1 = l1w + (size_t)j * Hd * 4 * Hd;
        const float* b1 = l1b + (size_t)j * 4 * Hd;
        const float* w2 = l2w + (size_t)j * 4 * Hd * Hd;
        const float* b2 = l2b + (size_t)j * Hd;
        const float* lg = ln_g + (size_t)j * Hd;
        const float* lb = ln_b + (size_t)j * Hd;
        const float* al = alpha + (size_t)j * 4 * Hd;

        packw_kernel<<<768, 256>>>(wq, wk, wv, wqkv);

        gemm_tc<<<dim3(6, 128), 256>>>(x, wqkv, qkv,
                                       Hd, Hd, 768, 768, nullptr, nullptr, 0);

        ktrans_kernel<<<dim3(8, 32, Bsz), dim3(32, 8)>>>(qkv, kt);

        flash_attn<<<dim3(8, Bsz * 4), 256, FL_SMEM>>>(qkv, kt, adjs, x, o);

        ln_kernel<<<Mrows, 256>>>(o, nullptr, lg, lb, tb);

        gemm_tc<<<dim3(8, 128), 256>>>(tb, w1, h1,
                                       Hd, Hd, 4 * Hd, 4 * Hd, b1, al, 1);
        gemm_tc<<<dim3(2, 128), 256>>>(h1, w2, h2,
                                       4 * Hd, 4 * Hd, Hd, Hd, b2, nullptr, 2);

        float* dst = (j == 1) ? out : x;
        ln_kernel<<<Mrows, 256>>>(h2, tb, lg, lb, dst);
    }

    int tail = out_size - XSZ;
    if (tail > 0)
        fill_tail_kernel<<<(tail + 255) / 256, 256>>>(out, XSZ, out_size);
}

// round 7
// speedup vs baseline: 17.3999x; 1.4532x over previous
#include <cuda_runtime.h>
#include <cuda_bf16.h>

// ---------------------------------------------------------------------------
// graph_encoder: B=16, N=1024, H=256, 4 heads (d=64), 2 layers.
// R6: bf16 m16n8k16 mma (fp32 accum) + bit-packed adjacency + occ-2 flash.
// ---------------------------------------------------------------------------

#define Bsz   16
#define Nn    1024
#define Hd    256
#define Ee    767
#define Rr    256
#define ROOTI 46
#define Mrows (Bsz * Nn)
#define XSZ   (Mrows * Hd)
#define H1SZ  (Mrows * 4 * Hd)
#define QKVSZ (Mrows * 3 * Hd)

__device__ float    g_x   [XSZ];
__device__ float    g_qkv [QKVSZ];   // [16384, 768] (q|k|v)
__device__ float    g_kt  [XSZ];     // [B, 256, 1024]
__device__ float    g_o   [XSZ];
__device__ float    g_t   [XSZ];
__device__ float    g_h2  [XSZ];
__device__ float    g_h1  [H1SZ];
__device__ float    g_wqkv[Hd * 3 * Hd];
__device__ unsigned g_adjb[Bsz * Nn * 32];   // bit-packed adjacency

// ---------------------------------------------------------------------------
__device__ __forceinline__ unsigned packbf(float lo, float hi)
{
    unsigned u;
    asm("cvt.rn.bf16x2.f32 %0, %1, %2;" : "=r"(u) : "f"(hi), "f"(lo));
    return u;
}

#define BF16_MMA(d, a, b)                                                     \
    asm volatile(                                                             \
        "mma.sync.aligned.m16n8k16.row.col.f32.bf16.bf16.f32 "                \
        "{%0,%1,%2,%3},{%4,%5,%6,%7},{%8,%9},{%0,%1,%2,%3};"                  \
        : "+f"((d)[0]), "+f"((d)[1]), "+f"((d)[2]), "+f"((d)[3])              \
        : "r"((a)[0]), "r"((a)[1]), "r"((a)[2]), "r"((a)[3]),                 \
          "r"((b)[0]), "r"((b)[1]))

// ---------------------------------------------------------------------------
__global__ void embed_kernel(const int* __restrict__ ents,
                             const int* __restrict__ rels,
                             const float* __restrict__ ent_table,
                             const float* __restrict__ rel_table,
                             float* __restrict__ x)
{
    int bn = blockIdx.x;
    int b  = bn >> 10;
    int n  = bn & 1023;
    const float* src;
    if (n < Ee)            src = ent_table + (size_t)ents[b * Ee + n] * Hd;
    else if (n < Ee + Rr)  src = rel_table + (size_t)rels[b * Rr + (n - Ee)] * Hd;
    else                   src = rel_table + (size_t)ROOTI * Hd;
    x[(size_t)bn * Hd + threadIdx.x] = src[threadIdx.x];
}

// ---------------------------------------------------------------------------
__global__ void packw_kernel(const float* __restrict__ wq,
                             const float* __restrict__ wk,
                             const float* __restrict__ wv,
                             float* __restrict__ out)
{
    int i = blockIdx.x * blockDim.x + threadIdx.x;
    int k = i / 768, c = i - k * 768;
    float v;
    if (c < 256)      v = wq[k * 256 + c];
    else if (c < 512) v = wk[k * 256 + c - 256];
    else              v = wv[k * 256 + c - 512];
    out[i] = v;
}

// ---------------------------------------------------------------------------
// Pack adjacency row bits: one warp per 32-entry word.
// grid 65536 x 256 threads (8 warps -> 8 words per block).
// ---------------------------------------------------------------------------
__global__ void adjpack_kernel(const int* __restrict__ adj,
                               unsigned* __restrict__ adjb)
{
    int gw   = blockIdx.x * 8 + (threadIdx.x >> 5);   // global word id
    int lane = threadIdx.x & 31;
    int row  = gw >> 5;
    int wrd  = gw & 31;
    int v = adj[((size_t)row << 10) + wrd * 32 + lane];
    unsigned m = __ballot_sync(0xffffffffu, v != 0);
    if (lane == 0) adjb[gw] = m;
}

// ---------------------------------------------------------------------------
// bf16 tensor-core GEMM: 128x128 block, 8 warps (2x4), warp tile 64x32,
// kstep 16 (m16n8k16). mode: 0 plain, 1 bias+PReLU, 2 bias.
// ---------------------------------------------------------------------------
__global__ void __launch_bounds__(256, 2)
gemm_tc(const float* __restrict__ A,
        const float* __restrict__ W,
        float* __restrict__ C,
        int K, int lda, int ldb, int ldc,
        const float* __restrict__ bias,
        const float* __restrict__ alpha,
        int mode)
{
    __shared__ unsigned As[2][8][132];   // word kw = k pair (2kw, 2kw+1), per row m
    __shared__ unsigned Bs[2][8][132];   // word kw per col n

    int t    = threadIdx.x;
    int w    = t >> 5, lane = t & 31;
    int gid  = lane >> 2, tid4 = lane & 3;
    int wm0  = (w >> 2) * 64;
    int wn0  = (w & 3) * 32;
    int row0 = blockIdx.y << 7;
    int col0 = blockIdx.x << 7;

    int am  = t >> 1;
    int aw0 = (t & 1) * 4;        // word offset (k offset = aw0*2)
    int bkw = t >> 5;             // 0..7
    int bc  = (t & 31) * 4;

    const float* Ap  = A + (size_t)(row0 + am) * lda + aw0 * 2;
    const float* Bp0 = W + (size_t)(bkw * 2) * ldb + col0 + bc;
    const float* Bp1 = Bp0 + ldb;

    {
        float4 a0 = *(const float4*)Ap;
        float4 a1 = *(const float4*)(Ap + 4);
        As[0][aw0 + 0][am] = packbf(a0.x, a0.y);
        As[0][aw0 + 1][am] = packbf(a0.z, a0.w);
        As[0][aw0 + 2][am] = packbf(a1.x, a1.y);
        As[0][aw0 + 3][am] = packbf(a1.z, a1.w);
        float4 b0 = *(const float4*)Bp0;
        float4 b1 = *(const float4*)Bp1;
        Bs[0][bkw][bc + 0] = packbf(b0.x, b1.x);
        Bs[0][bkw][bc + 1] = packbf(b0.y, b1.y);
        Bs[0][bkw][bc + 2] = packbf(b0.z, b1.z);
        Bs[0][bkw][bc + 3] = packbf(b0.w, b1.w);
    }
    __syncthreads();

    float acc[4][4][4] = {};
    int buf = 0;

    for (int k0 = 16; k0 <= K; k0 += 16) {
        float4 na0, na1, nb0, nb1;
        if (k0 < K) {
            na0 = *(const float4*)(Ap + k0);
            na1 = *(const float4*)(Ap + k0 + 4);
            nb0 = *(const float4*)(Bp0 + (size_t)k0 * ldb);
            nb1 = *(const float4*)(Bp1 + (size_t)k0 * ldb);
        }
        {
            unsigned af[4][4], bf[4][2];
#pragma unroll
            for (int nt = 0; nt < 4; nt++) {
                bf[nt][0] = Bs[buf][tid4][wn0 + nt * 8 + gid];
                bf[nt][1] = Bs[buf][tid4 + 4][wn0 + nt * 8 + gid];
            }
#pragma unroll
            for (int mt = 0; mt < 4; mt++) {
                af[mt][0] = As[buf][tid4][wm0 + mt * 16 + gid];
                af[mt][1] = As[buf][tid4][wm0 + mt * 16 + gid + 8];
                af[mt][2] = As[buf][tid4 + 4][wm0 + mt * 16 + gid];
                af[mt][3] = As[buf][tid4 + 4][wm0 + mt * 16 + gid + 8];
            }
#pragma unroll
            for (int mt = 0; mt < 4; mt++)
#pragma unroll
                for (int nt = 0; nt < 4; nt++)
                    BF16_MMA(acc[mt][nt], af[mt], bf[nt]);
        }
        if (k0 < K) {
            buf ^= 1;
            As[buf][aw0 + 0][am] = packbf(na0.x, na0.y);
            As[buf][aw0 + 1][am] = packbf(na0.z, na0.w);
            As[buf][aw0 + 2][am] = packbf(na1.x, na1.y);
            As[buf][aw0 + 3][am] = packbf(na1.z, na1.w);
            Bs[buf][bkw][bc + 0] = packbf(nb0.x, nb1.x);
            Bs[buf][bkw][bc + 1] = packbf(nb0.y, nb1.y);
            Bs[buf][bkw][bc + 2] = packbf(nb0.z, nb1.z);
            Bs[buf][bkw][bc + 3] = packbf(nb0.w, nb1.w);
            __syncthreads();
        }
    }

#pragma unroll
    for (int mt = 0; mt < 4; mt++) {
        int r0 = row0 + wm0 + mt * 16 + gid;
#pragma unroll
        for (int nt = 0; nt < 4; nt++) {
            int c = col0 + wn0 + nt * 8 + 2 * tid4;
            float v0 = acc[mt][nt][0], v1 = acc[mt][nt][1];
            float v2 = acc[mt][nt][2], v3 = acc[mt][nt][3];
            if (mode != 0) {
                float b0v = bias[c], b1v = bias[c + 1];
                v0 += b0v; v1 += b1v; v2 += b0v; v3 += b1v;
            }
            if (mode == 1) {
                float a0v = alpha[c], a1v = alpha[c + 1];
                v0 = v0 >= 0.f ? v0 : a0v * v0;
                v1 = v1 >= 0.f ? v1 : a1v * v1;
                v2 = v2 >= 0.f ? v2 : a0v * v2;
                v3 = v3 >= 0.f ? v3 : a1v * v3;
            }
            *(float2*)&C[(size_t)r0 * ldc + c]       = make_float2(v0, v1);
            *(float2*)&C[(size_t)(r0 + 8) * ldc + c] = make_float2(v2, v3);
        }
    }
}

// ---------------------------------------------------------------------------
__global__ void ktrans_kernel(const float* __restrict__ qkv, float* __restrict__ Kt)
{
    __shared__ float tile[32][33];
    int b  = blockIdx.z;
    int j0 = blockIdx.y << 5;
    int c0 = blockIdx.x << 5;
    int tx = threadIdx.x;
    int ty = threadIdx.y;
    const float* src = qkv + (size_t)b * Nn * 768 + 256;
#pragma unroll
    for (int r = ty; r < 32; r += 8)
        tile[r][tx] = src[(size_t)(j0 + r) * 768 + c0 + tx];
    __syncthreads();
    float* dst = Kt + (size_t)b * Hd * Nn;
#pragma unroll
    for (int r = ty; r < 32; r += 8)
        dst[(size_t)(c0 + r) * Nn + j0 + tx] = tile[tx][r];
}

// ---------------------------------------------------------------------------
// Fused flash attention (bf16 mma, fp32 softmax state). grid (8, 64), 256 thr.
// Smem (u32 words): Qs[32][136] Ks[32][136] Vs[64][72] Ps[64][136] red[2*512]
// ---------------------------------------------------------------------------
#define FL_QS   0
#define FL_KS   (32 * 136)
#define FL_VS   (FL_KS + 32 * 136)
#define FL_PS   (FL_VS + 64 * 72)
#define FL_RED  (FL_PS + 64 * 136)
#define FL_SMEM ((FL_RED + 2 * 4 * 128) * 4)

__global__ void __launch_bounds__(256, 2)
flash_attn(const float* __restrict__ qkv,
           const float* __restrict__ Kt,
           const unsigned* __restrict__ adjb,
           const float* __restrict__ X,
           float* __restrict__ O)
{
    extern __shared__ unsigned sm[];
    unsigned* Qs = sm + FL_QS;
    unsigned* Ks = sm + FL_KS;
    unsigned* Vs = sm + FL_VS;
    unsigned* Ps = sm + FL_PS;
    float* redm = (float*)(sm + FL_RED);
    float* reds = redm + 4 * 128;

    int t = threadIdx.x;
    int w = t >> 5, lane = t & 31;
    int gid = lane >> 2, tid4 = lane & 3;
    int wm0 = (w >> 2) * 64;
    int wn0 = (w & 3) * 32;
    int wd0 = (w & 3) * 16;
    int z = blockIdx.y;
    int b = z >> 2, h = z & 3;
    int i0 = blockIdx.x << 7;

    // ---- Q tile: Qs[dw][i] (bf16x2 along d), once ----
    {
        int i   = t >> 1;
        int dw0 = (t & 1) * 16;
        const float* src = qkv + (size_t)(b * Nn + i0 + i) * 768 + h * 64 + dw0 * 2;
#pragma unroll
        for (int c = 0; c < 16; c += 2) {
            float4 v = *(const float4*)(src + 2 * c);
            Qs[(dw0 + c) * 136 + i]     = packbf(v.x, v.y);
            Qs[(dw0 + c + 1) * 136 + i] = packbf(v.z, v.w);
        }
    }

    float m_st[8], l_st[8];
    float oac[4][2][4] = {};
#pragma unroll
    for (int s = 0; s < 8; s++) { m_st[s] = -1e4f; l_st[s] = 0.f; }

    for (int jt = 0; jt < 8; jt++) {
        int j0 = jt << 7;
        __syncthreads();   // protect Ks/Vs/Ps (and Qs first iter)

        // ---- K tile: Ks[dw][j] (pairs across two d rows of Kt) ----
        {
            int dw = t >> 3;
            int jc = (t & 7) * 16;
            const float* r0 = Kt + ((size_t)b * Hd + h * 64 + 2 * dw) * Nn + j0 + jc;
            const float* r1 = r0 + Nn;
#pragma unroll
            for (int c = 0; c < 16; c += 4) {
                float4 x0 = *(const float4*)(r0 + c);
                float4 x1 = *(const float4*)(r1 + c);
                Ks[dw * 136 + jc + c + 0] = packbf(x0.x, x1.x);
                Ks[dw * 136 + jc + c + 1] = packbf(x0.y, x1.y);
                Ks[dw * 136 + jc + c + 2] = packbf(x0.z, x1.z);
                Ks[dw * 136 + jc + c + 3] = packbf(x0.w, x1.w);
            }
        }
        // ---- V tile: Vs[jw][d] (pairs across two j rows) ----
        {
            int jw = t >> 2;
            int dc = (t & 3) * 16;
            const float* r0 = qkv + (size_t)(b * Nn + j0 + 2 * jw) * 768 + 512 + h * 64 + dc;
            const float* r1 = r0 + 768;
#pragma unroll
            for (int c = 0; c < 16; c += 4) {
                float4 x0 = *(const float4*)(r0 + c);
                float4 x1 = *(const float4*)(r1 + c);
                Vs[jw * 72 + dc + c + 0] = packbf(x0.x, x1.x);
                Vs[jw * 72 + dc + c + 1] = packbf(x0.y, x1.y);
                Vs[jw * 72 + dc + c + 2] = packbf(x0.z, x1.z);
                Vs[jw * 72 + dc + c + 3] = packbf(x0.w, x1.w);
            }
        }
        __syncthreads();

        // ---- S = Q @ K^T (128x128, k=64) ----
        float sac[4][4][4] = {};
#pragma unroll
        for (int ko = 0; ko < 32; ko += 8) {
            unsigned af[4][4], bf[4][2];
#pragma unroll
            for (int nt = 0; nt < 4; nt++) {
                bf[nt][0] = Ks[(ko + tid4) * 136 + wn0 + nt * 8 + gid];
                bf[nt][1] = Ks[(ko + tid4 + 4) * 136 + wn0 + nt * 8 + gid];
            }
#pragma unroll
            for (int mt = 0; mt < 4; mt++) {
                af[mt][0] = Qs[(ko + tid4) * 136 + wm0 + mt * 16 + gid];
                af[mt][1] = Qs[(ko + tid4) * 136 + wm0 + mt * 16 + gid + 8];
                af[mt][2] = Qs[(ko + tid4 + 4) * 136 + wm0 + mt * 16 + gid];
                af[mt][3] = Qs[(ko + tid4 + 4) * 136 + wm0 + mt * 16 + gid + 8];
            }
#pragma unroll
            for (int mt = 0; mt < 4; mt++)
#pragma unroll
                for (int nt = 0; nt < 4; nt++)
                    BF16_MMA(sac[mt][nt], af[mt], bf[nt]);
        }

        // ---- mask (bitpacked) + scale, per-row tile max ----
        int wq = (j0 + wn0) >> 5;
        float tmax[8];
#pragma unroll
        for (int s = 0; s < 8; s++) tmax[s] = -1e30f;
#pragma unroll
        for (int mt = 0; mt < 4; mt++) {
            int r = i0 + wm0 + mt * 16 + gid;
            unsigned w0 = adjb[(((size_t)(b * Nn + r)) << 5) + wq];
            unsigned w1 = adjb[(((size_t)(b * Nn + r + 8)) << 5) + wq];
#pragma unroll
            for (int nt = 0; nt < 4; nt++) {
                int bit = nt * 8 + 2 * tid4;
                sac[mt][nt][0] = (w0 >> bit) & 1        ? sac[mt][nt][0] * 0.0625f : -1e30f;
                sac[mt][nt][1] = (w0 >> (bit + 1)) & 1  ? sac[mt][nt][1] * 0.0625f : -1e30f;
                sac[mt][nt][2] = (w1 >> bit) & 1        ? sac[mt][nt][2] * 0.0625f : -1e30f;
                sac[mt][nt][3] = (w1 >> (bit + 1)) & 1  ? sac[mt][nt][3] * 0.0625f : -1e30f;
                tmax[mt * 2 + 0] = fmaxf(tmax[mt * 2 + 0],
                                         fmaxf(sac[mt][nt][0], sac[mt][nt][1]));
                tmax[mt * 2 + 1] = fmaxf(tmax[mt * 2 + 1],
                                         fmaxf(sac[mt][nt][2], sac[mt][nt][3]));
            }
        }
#pragma unroll
        for (int s = 0; s < 8; s++) {
            tmax[s] = fmaxf(tmax[s], __shfl_xor_sync(0xffffffffu, tmax[s], 1));
            tmax[s] = fmaxf(tmax[s], __shfl_xor_sync(0xffffffffu, tmax[s], 2));
        }
        if (tid4 == 0) {
#pragma unroll
            for (int mt = 0; mt < 4; mt++) {
                redm[(w & 3) * 128 + wm0 + mt * 16 + gid]     = tmax[mt * 2];
                redm[(w & 3) * 128 + wm0 + mt * 16 + gid + 8] = tmax[mt * 2 + 1];
            }
        }
        __syncthreads();

        float alp[8];
#pragma unroll
        for (int mt = 0; mt < 4; mt++)
#pragma unroll
            for (int q = 0; q < 2; q++) {
                int r = wm0 + mt * 16 + gid + q * 8;
                float tm = fmaxf(fmaxf(redm[r], redm[128 + r]),
                                 fmaxf(redm[256 + r], redm[384 + r]));
                int s = mt * 2 + q;
                float mn = fmaxf(m_st[s], fmaxf(tm, -1e4f));
                alp[s] = __expf(m_st[s] - mn);
                m_st[s] = mn;
            }

        // ---- exp, partial sums, store P (bf16 pairs along j) ----
        float psum[8] = {};
#pragma unroll
        for (int mt = 0; mt < 4; mt++) {
            int r = wm0 + mt * 16 + gid;
            int s0 = mt * 2, s1 = mt * 2 + 1;
#pragma unroll
            for (int nt = 0; nt < 4; nt++) {
                int cw = (wn0 >> 1) + nt * 4 + tid4;   // word index (pair of j)
                float e0 = __expf(sac[mt][nt][0] - m_st[s0]);
                float e1 = __expf(sac[mt][nt][1] - m_st[s0]);
                float e2 = __expf(sac[mt][nt][2] - m_st[s1]);
                float e3 = __expf(sac[mt][nt][3] - m_st[s1]);
                psum[s0] += e0 + e1;
                psum[s1] += e2 + e3;
                Ps[cw * 136 + r]     = packbf(e0, e1);
                Ps[cw * 136 + r + 8] = packbf(e2, e3);
            }
        }
#pragma unroll
        for (int s = 0; s < 8; s++) {
            psum[s] += __shfl_xor_sync(0xffffffffu, psum[s], 1);
            psum[s] += __shfl_xor_sync(0xffffffffu, psum[s], 2);
        }
        if (tid4 == 0) {
#pragma unroll
            for (int mt = 0; mt < 4; mt++) {
                reds[(w & 3) * 128 + wm0 + mt * 16 + gid]     = psum[mt * 2];
                reds[(w & 3) * 128 + wm0 + mt * 16 + gid + 8] = psum[mt * 2 + 1];
            }
        }
        __syncthreads();

        // ---- update l, rescale O ----
#pragma unroll
        for (int mt = 0; mt < 4; mt++)
#pragma unroll
            for (int q = 0; q < 2; q++) {
                int r = wm0 + mt * 16 + gid + q * 8;
                int s = mt * 2 + q;
                float ps = reds[r] + reds[128 + r] + reds[256 + r] + reds[384 + r];
                l_st[s] = l_st[s] * alp[s] + ps;
            }
#pragma unroll
        for (int mt = 0; mt < 4; mt++)
#pragma unroll
            for (int nt = 0; nt < 2; nt++) {
                oac[mt][nt][0] *= alp[mt * 2];
                oac[mt][nt][1] *= alp[mt * 2];
                oac[mt][nt][2] *= alp[mt * 2 + 1];
                oac[mt][nt][3] *= alp[mt * 2 + 1];
            }

        // ---- O += P @ V (128x64, k=128 -> 64 words) ----
#pragma unroll
        for (int ko = 0; ko < 64; ko += 8) {
            unsigned af[4][4], bf[2][2];
#pragma unroll
            for (int nt = 0; nt < 2; nt++) {
                bf[nt][0] = Vs[(ko + tid4) * 72 + wd0 + nt * 8 + gid];
                bf[nt][1] = Vs[(ko + tid4 + 4) * 72 + wd0 + nt * 8 + gid];
            }
#pragma unroll
            for (int mt = 0; mt < 4; mt++) {
                af[mt][0] = Ps[(ko + tid4) * 136 + wm0 + mt * 16 + gid];
                af[mt][1] = Ps[(ko + tid4) * 136 + wm0 + mt * 16 + gid + 8];
                af[mt][2] = Ps[(ko + tid4 + 4) * 136 + wm0 + mt * 16 + gid];
                af[mt][3] = Ps[(ko + tid4 + 4) * 136 + wm0 + mt * 16 + gid + 8];
            }
#pragma unroll
            for (int mt = 0; mt < 4; mt++)
#pragma unroll
                for (int nt = 0; nt < 2; nt++)
                    BF16_MMA(oac[mt][nt], af[mt], bf[nt]);
        }
    }

    // ---- epilogue: O/l + residual X ----
    float inv[8];
#pragma unroll
    for (int s = 0; s < 8; s++) inv[s] = 1.f / l_st[s];
#pragma unroll
    for (int mt = 0; mt < 4; mt++) {
        int r = i0 + wm0 + mt * 16 + gid;
#pragma unroll
        for (int nt = 0; nt < 2; nt++) {
            int c = wd0 + nt * 8 + 2 * tid4;
            size_t idx0 = (size_t)(b * Nn + r) * Hd + h * 64 + c;
            size_t idx1 = (size_t)(b * Nn + r + 8) * Hd + h * 64 + c;
            float2 x0 = *(const float2*)&X[idx0];
            float2 x1 = *(const float2*)&X[idx1];
            float2 o0 = make_float2(oac[mt][nt][0] * inv[mt * 2] + x0.x,
                                    oac[mt][nt][1] * inv[mt * 2] + x0.y);
            float2 o1 = make_float2(oac[mt][nt][2] * inv[mt * 2 + 1] + x1.x,
                                    oac[mt][nt][3] * inv[mt * 2 + 1] + x1.y);
            *(float2*)&O[idx0] = o0;
            *(float2*)&O[idx1] = o1;
        }
    }
}

// ---------------------------------------------------------------------------
__global__ void ln_kernel(const float* __restrict__ A,
                          const float* __restrict__ Badd,
                          const float* __restrict__ gamma,
                          const float* __restrict__ beta,
                          float* __restrict__ out)
{
    __shared__ float red[256];
    int row = blockIdx.x;
    int t   = threadIdx.x;
    size_t idx = (size_t)row * Hd + t;
    float v = A[idx];
    if (Badd) v += Badd[idx];

    red[t] = v;
    __syncthreads();
#pragma unroll
    for (int off = 128; off > 0; off >>= 1) {
        if (t < off) red[t] += red[t + off];
        __syncthreads();
    }
    float mean = red[0] * (1.f / Hd);
    __syncthreads();

    float d = v - mean;
    red[t] = d * d;
    __syncthreads();
#pragma unroll
    for (int off = 128; off > 0; off >>= 1) {
        if (t < off) red[t] += red[t + off];
        __syncthreads();
    }
    float var = red[0] * (1.f / Hd);
    out[idx] = d * rsqrtf(var + 1e-5f) * gamma[t] + beta[t];
}

// ---------------------------------------------------------------------------
__global__ void fill_tail_kernel(float* __restrict__ out, int start, int total)
{
    int i = blockIdx.x * blockDim.x + threadIdx.x + start;
    if (i < total) out[i] = 1.0f;
}

// ---------------------------------------------------------------------------
extern "C" void kernel_launch(void* const* d_in, const int* in_sizes, int n_in,
                              void* d_out, int out_size)
{
    const int*   ents      = (const int*)  d_in[0];
    const int*   rels      = (const int*)  d_in[1];
    const int*   adjs      = (const int*)  d_in[2];
    const float* ent_table = (const float*)d_in[3];
    const float* rel_table = (const float*)d_in[4];
    const float* Wq        = (const float*)d_in[5];
    const float* Wk        = (const float*)d_in[6];
    const float* Wv        = (const float*)d_in[7];
    const float* l1w       = (const float*)d_in[8];
    const float* l1b       = (const float*)d_in[9];
    const float* l2w       = (const float*)d_in[10];
    const float* l2b       = (const float*)d_in[11];
    const float* ln_g      = (const float*)d_in[12];
    const float* ln_b      = (const float*)d_in[13];
    const float* alpha     = (const float*)d_in[14];
    float* out = (float*)d_out;

    float *x, *qkv, *kt, *o, *tb, *h1, *h2, *wqkv;
    unsigned* adjb;
    cudaGetSymbolAddress((void**)&x,    g_x);
    cudaGetSymbolAddress((void**)&qkv,  g_qkv);
    cudaGetSymbolAddress((void**)&kt,   g_kt);
    cudaGetSymbolAddress((void**)&o,    g_o);
    cudaGetSymbolAddress((void**)&tb,   g_t);
    cudaGetSymbolAddress((void**)&h1,   g_h1);
    cudaGetSymbolAddress((void**)&h2,   g_h2);
    cudaGetSymbolAddress((void**)&wqkv, g_wqkv);
    cudaGetSymbolAddress((void**)&adjb, g_adjb);

    cudaFuncSetAttribute(flash_attn, cudaFuncAttributeMaxDynamicSharedMemorySize,
                         FL_SMEM);

    embed_kernel<<<Bsz * Nn, 256>>>(ents, rels, ent_table, rel_table, x);
    adjpack_kernel<<<Bsz * Nn * 32 / 8, 256>>>(adjs, adjb);

    for (int j = 0; j < 2; j++) {
        const float* wq = Wq  + (size_t)j * Hd * Hd;
        const float* wk = Wk  + (size_t)j * Hd * Hd;
        const float* wv = Wv  + (size_t)j * Hd * Hd;
        const float* w1 = l1w + (size_t)j * Hd * 4 * Hd;
        const float* b1 = l1b + (size_t)j * 4 * Hd;
        const float* w2 = l2w + (size_t)j * 4 * Hd * Hd;
        const float* b2 = l2b + (size_t)j * Hd;
        const float* lg = ln_g + (size_t)j * Hd;
        const float* lb = ln_b + (size_t)j * Hd;
        const float* al = alpha + (size_t)j * 4 * Hd;

        packw_kernel<<<768, 256>>>(wq, wk, wv, wqkv);

        gemm_tc<<<dim3(6, 128), 256>>>(x, wqkv, qkv,
                                       Hd, Hd, 768, 768, nullptr, nullptr, 0);

        ktrans_kernel<<<dim3(8, 32, Bsz), dim3(32, 8)>>>(qkv, kt);

        flash_attn<<<dim3(8, Bsz * 4), 256, FL_SMEM>>>(qkv, kt, adjb, x, o);

        ln_kernel<<<Mrows, 256>>>(o, nullptr, lg, lb, tb);

        gemm_tc<<<dim3(8, 128), 256>>>(tb, w1, h1,
                                       Hd, Hd, 4 * Hd, 4 * Hd, b1, al, 1);
        gemm_tc<<<dim3(2, 128), 256>>>(h1, w2, h2,
                                       4 * Hd, 4 * Hd, Hd, Hd, b2, nullptr, 2);

        float* dst = (j == 1) ? out : x;
        ln_kernel<<<Mrows, 256>>>(h2, tb, lg, lb, dst);
    }

    int tail = out_size - XSZ;
    if (tail > 0)
        fill_tail_kernel<<<(tail + 255) / 256, 256>>>(out, XSZ, out_size);
}